// round 3
// baseline (speedup 1.0000x reference)
#include <cuda_runtime.h>
#include <cuda_bf16.h>

#define NN 4096
#define ITERS 10
#define SWEEPS 7
#define MV_BLOCKS 128
#define MV_TPB 512

// ---------------- persistent device scratch (static, no runtime alloc) ----------------
__device__ __nv_bfloat16 g_D16[(size_t)NN * NN];   // lamda1 * D_tilda in bf16 (33.5 MB)
__device__ float g_qr[NN];        // q + rho
__device__ float g_Minv[NN];      // Jacobi preconditioner
__device__ float g_StS[64 * 64];  // lamda2 * S^T S
__device__ float g_x[NN], g_r[NN], g_z[NN], g_p[NN], g_Ap[NN];
__device__ float g_zAzA[ITERS], g_zApA[ITERS], g_rzA[ITERS], g_pApA[ITERS];
__device__ int   g_barA[ITERS];

// ---------------- 1) setup: StS, b, Minv, CG state, zero reductions/barriers ----------
__global__ void __launch_bounds__(1024) setup_kernel(
    const float* __restrict__ inp, const float* __restrict__ L,
    const void* __restrict__ maskv, const float* __restrict__ thP,
    const float* __restrict__ D,
    const float* __restrict__ l1p, const float* __restrict__ l2p,
    const float* __restrict__ rhop, const float* __restrict__ S)
{
    __shared__ float Ss[64 * 65];
    __shared__ float Ts[64 * 65];
    int t = threadIdx.x;
    float l1 = *l1p, l2 = *l2p, rho = *rhop;

    // detect mask storage: 4-byte words (int32 0/1 or float 0.0/1.0) vs packed bytes
    const unsigned* maskw = (const unsigned*)maskv;
    unsigned wvd = maskw[t];  // t<1024: in-bounds for both layouts
    int bad = (wvd != 0u && wvd != 1u && wvd != 0x3F800000u) ? 1 : 0;
    int bytemode = __syncthreads_or(bad);

    for (int i = t; i < 4096; i += 1024) {
        int h = i >> 6, a = i & 63;
        Ss[h * 65 + a] = S[i];
    }
    __syncthreads();
    for (int e = t; e < 4096; e += 1024) {
        int a = e >> 6, b = e & 63;
        float acc = 0.f;
        #pragma unroll 8
        for (int h = 0; h < 64; h++) acc += Ss[h * 65 + a] * Ss[h * 65 + b];
        acc *= l2;
        Ts[a * 65 + b] = acc;
        g_StS[e] = acc;
    }
    __syncthreads();
    const unsigned char* maskb = (const unsigned char*)maskv;
    for (int n = t; n < NN; n += 1024) {
        float qf;
        if (bytemode) qf = (maskb[n] != 0) ? 1.f : 0.f;
        else          qf = (maskw[n] != 0u) ? 1.f : 0.f;
        float qr = qf + rho;
        g_qr[n] = qr;
        int c = n & 63;
        float dg = D[(size_t)n * (NN + 1)];          // diag(D_tilda)
        float denom = qr + l1 * dg + Ts[c * 65 + c];
        float minv = 1.f / denom;
        g_Minv[n] = minv;
        float bb = rho * (L[n] - thP[n]) + (qf != 0.f ? inp[n] : 0.f);
        g_r[n] = bb;
        g_z[n] = minv * bb;
        g_x[n] = 0.f; g_p[n] = 0.f; g_Ap[n] = 0.f;
    }
    if (t < ITERS) {
        g_zAzA[t] = 0.f; g_zApA[t] = 0.f; g_rzA[t] = 0.f; g_pApA[t] = 0.f;
        g_barA[t] = 0;
    }
}

// ---------------- 2) matvec + fused dots + grid barrier + fused PCG update ------------
// FIRST variant reads fp32 D, scales by lamda1, writes bf16 copy (used thereafter).
// 128 blocks x 512 threads; block owns 32 consecutive rows (all same h); 2 rows/warp.
template <bool FIRST>
__global__ void __launch_bounds__(MV_TPB) matvec_kernel(
    const float* __restrict__ Dfp32, const float* __restrict__ l1p, int k)
{
    __shared__ __align__(16) float zs[NN];   // 16 KB
    __shared__ float Tss[64 * 33];           // 8.4 KB: StS cols u0..u0+31 (scaled)
    __shared__ float az_s[32];
    __shared__ float sred[3];
    int t = threadIdx.x;
    int b = blockIdx.x;
    int row0 = b * 32;
    int h = row0 >> 6;
    int u0 = (b & 1) * 32;
    if (t < 3) sred[t] = 0.f;
    for (int i = t; i < NN; i += MV_TPB) zs[i] = g_z[i];
    for (int i = t; i < 64 * 32; i += MV_TPB) {
        int bb = i >> 5, uu = i & 31;
        Tss[bb * 33 + uu] = g_StS[bb * 64 + u0 + uu];
    }
    __syncthreads();

    int warp = t >> 5, lane = t & 31;
    int r0 = row0 + 2 * warp, r1 = r0 + 1;
    float acc0 = 0.f, acc1 = 0.f;

    if (FIRST) {
        float l1 = *l1p;
        const float4* d0 = (const float4*)(Dfp32 + (size_t)r0 * NN);
        const float4* d1 = (const float4*)(Dfp32 + (size_t)r1 * NN);
        __nv_bfloat162* w0 = (__nv_bfloat162*)(g_D16 + (size_t)r0 * NN);
        __nv_bfloat162* w1 = (__nv_bfloat162*)(g_D16 + (size_t)r1 * NN);
        #pragma unroll 4
        for (int j = 0; j < 32; j++) {
            int idx = lane + 32 * j;
            float4 z4 = ((const float4*)zs)[idx];
            float4 a = d0[idx];
            float4 c = d1[idx];
            __nv_bfloat162 a01, a23, c01, c23;
            a01.x = __float2bfloat16_rn(a.x * l1); a01.y = __float2bfloat16_rn(a.y * l1);
            a23.x = __float2bfloat16_rn(a.z * l1); a23.y = __float2bfloat16_rn(a.w * l1);
            c01.x = __float2bfloat16_rn(c.x * l1); c01.y = __float2bfloat16_rn(c.y * l1);
            c23.x = __float2bfloat16_rn(c.z * l1); c23.y = __float2bfloat16_rn(c.w * l1);
            w0[2 * idx] = a01; w0[2 * idx + 1] = a23;
            w1[2 * idx] = c01; w1[2 * idx + 1] = c23;
            // accumulate with ROUNDED values so the CG operator is fixed across iters
            float2 f;
            f = __bfloat1622float2(a01); acc0 += f.x * z4.x + f.y * z4.y;
            f = __bfloat1622float2(a23); acc0 += f.x * z4.z + f.y * z4.w;
            f = __bfloat1622float2(c01); acc1 += f.x * z4.x + f.y * z4.y;
            f = __bfloat1622float2(c23); acc1 += f.x * z4.z + f.y * z4.w;
        }
    } else {
        const uint4* d0 = (const uint4*)(g_D16 + (size_t)r0 * NN);
        const uint4* d1 = (const uint4*)(g_D16 + (size_t)r1 * NN);
        #pragma unroll 4
        for (int j = 0; j < 16; j++) {
            int idx = lane + 32 * j;
            float4 za = ((const float4*)zs)[2 * idx];
            float4 zb = ((const float4*)zs)[2 * idx + 1];
            uint4 u = d0[idx];
            float2 p0 = __bfloat1622float2(*(__nv_bfloat162*)&u.x);
            float2 p1 = __bfloat1622float2(*(__nv_bfloat162*)&u.y);
            float2 p2 = __bfloat1622float2(*(__nv_bfloat162*)&u.z);
            float2 p3 = __bfloat1622float2(*(__nv_bfloat162*)&u.w);
            acc0 += p0.x * za.x + p0.y * za.y + p1.x * za.z + p1.y * za.w
                  + p2.x * zb.x + p2.y * zb.y + p3.x * zb.z + p3.y * zb.w;
            uint4 v = d1[idx];
            p0 = __bfloat1622float2(*(__nv_bfloat162*)&v.x);
            p1 = __bfloat1622float2(*(__nv_bfloat162*)&v.y);
            p2 = __bfloat1622float2(*(__nv_bfloat162*)&v.z);
            p3 = __bfloat1622float2(*(__nv_bfloat162*)&v.w);
            acc1 += p0.x * za.x + p0.y * za.y + p1.x * za.z + p1.y * za.w
                  + p2.x * zb.x + p2.y * zb.y + p3.x * zb.z + p3.y * zb.w;
        }
    }

    // lamda2 * (Z @ StS) term: row n=(h,u) needs sum_b StS[b][u]*z[h*64+b]
    {
        int uu0 = (r0 & 63) - u0;
        int uu1 = uu0 + 1;
        float zl = zs[(h << 6) + lane];
        float zh2 = zs[(h << 6) + lane + 32];
        acc0 += Tss[lane * 33 + uu0] * zl + Tss[(lane + 32) * 33 + uu0] * zh2;
        acc1 += Tss[lane * 33 + uu1] * zl + Tss[(lane + 32) * 33 + uu1] * zh2;
    }
    #pragma unroll
    for (int off = 16; off; off >>= 1) {
        acc0 += __shfl_xor_sync(0xffffffffu, acc0, off);
        acc1 += __shfl_xor_sync(0xffffffffu, acc1, off);
    }
    if (lane < 2) {
        int row = r0 + lane;
        float a = lane ? acc1 : acc0;
        float zr = zs[row];
        float Azv = a + g_qr[row] * zr;
        az_s[2 * warp + lane] = Azv;
        atomicAdd(&sred[0], zr * Azv);         // z'Az
        atomicAdd(&sred[1], zr * g_Ap[row]);   // z'Ap_old
        atomicAdd(&sred[2], g_r[row] * zr);    // r'z
    }
    __syncthreads();

    // software grid barrier (128 co-resident blocks)
    if (t == 0) {
        atomicAdd(&g_zAzA[k], sred[0]);
        atomicAdd(&g_zApA[k], sred[1]);
        atomicAdd(&g_rzA[k],  sred[2]);
        __threadfence();
        atomicAdd(&g_barA[k], 1);
        while (atomicAdd(&g_barA[k], 0) < MV_BLOCKS) __nanosleep(64);
    }
    __syncthreads();

    // fused PCG update for OWN 32 rows
    if (t < 32) {
        float zAz = atomicAdd(&g_zAzA[k], 0.f);
        float zAp = atomicAdd(&g_zApA[k], 0.f);
        float rz  = atomicAdd(&g_rzA[k],  0.f);
        float beta = 0.f, pApprev = 0.f;
        if (k > 0) {
            float rzp = g_rzA[k - 1];     // finalized in previous launch
            beta = (rzp != 0.f) ? rz / rzp : 0.f;
            pApprev = g_pApA[k - 1];
        }
        float pAp = zAz + 2.f * beta * zAp + beta * beta * pApprev;
        float alpha = (pAp != 0.f) ? rz / pAp : 0.f;
        int row = row0 + t;
        float zn = zs[row];
        float pn = zn + beta * g_p[row];
        float Apn = az_s[t] + beta * g_Ap[row];
        g_p[row] = pn; g_Ap[row] = Apn;
        g_x[row] = g_x[row] + alpha * pn;
        float rn = g_r[row] - alpha * Apn;
        g_r[row] = rn;
        g_z[row] = g_Minv[row] * rn;
        if (t == 0 && b == 0) g_pApA[k] = pAp;
    }
}

// ---------------- 3) SVT via ONE-SIDED Jacobi SVD of M (single block) ----------------
// C starts as M = x + th_P (column-major); rotations orthogonalize column pairs.
// M V = C = U diag(s); s_c = ||C[:,c]||; Ltmp = C diag(w) V^T, w = (s - tau)_+/s.
__global__ void __launch_bounds__(1024) svt_kernel(
    const float* __restrict__ thP, const float* __restrict__ vp,
    const float* __restrict__ netap, float* __restrict__ out)
{
    __shared__ float C[64 * 65];  // col c at C[c*65 + r]
    __shared__ float V[64 * 65];
    __shared__ float sv[64], wv[64];
    __shared__ float smax_s;
    int t = threadIdx.x, warp = t >> 5, lane = t & 31;

    for (int i = t; i < 4096; i += 1024) {
        int r = i & 63, c = i >> 6;
        C[c * 65 + r] = g_x[r * 64 + c] + thP[r * 64 + c];
        V[c * 65 + r] = (r == c) ? 1.f : 0.f;
    }
    __syncthreads();

    for (int sw = 0; sw < SWEEPS; sw++) {
        for (int rr = 0; rr < 63; rr++) {
            int p = (warp == 0) ? 0 : (1 + ((warp - 1 + rr) % 63));
            int q = 1 + ((62 - warp + rr) % 63);
            float cp0 = C[p * 65 + lane], cp1 = C[p * 65 + lane + 32];
            float cq0 = C[q * 65 + lane], cq1 = C[q * 65 + lane + 32];
            float app = cp0 * cp0 + cp1 * cp1;
            float aqq = cq0 * cq0 + cq1 * cq1;
            float apq = cp0 * cq0 + cp1 * cq1;
            #pragma unroll
            for (int off = 16; off; off >>= 1) {
                app += __shfl_xor_sync(0xffffffffu, app, off);
                aqq += __shfl_xor_sync(0xffffffffu, aqq, off);
                apq += __shfl_xor_sync(0xffffffffu, apq, off);
            }
            float c_ = 1.f, s_ = 0.f;
            if (lane == 0 && apq != 0.f) {
                float th = (aqq - app) / (2.f * apq);
                float tt = 1.f / (fabsf(th) + sqrtf(th * th + 1.f));
                if (th < 0.f) tt = -tt;
                c_ = rsqrtf(1.f + tt * tt);
                s_ = tt * c_;
            }
            c_ = __shfl_sync(0xffffffffu, c_, 0);
            s_ = __shfl_sync(0xffffffffu, s_, 0);
            C[p * 65 + lane]      = c_ * cp0 - s_ * cq0;
            C[q * 65 + lane]      = s_ * cp0 + c_ * cq0;
            C[p * 65 + lane + 32] = c_ * cp1 - s_ * cq1;
            C[q * 65 + lane + 32] = s_ * cp1 + c_ * cq1;
            float vp0 = V[p * 65 + lane], vp1 = V[p * 65 + lane + 32];
            float vq0 = V[q * 65 + lane], vq1 = V[q * 65 + lane + 32];
            V[p * 65 + lane]      = c_ * vp0 - s_ * vq0;
            V[q * 65 + lane]      = s_ * vp0 + c_ * vq0;
            V[p * 65 + lane + 32] = c_ * vp1 - s_ * vq1;
            V[q * 65 + lane + 32] = s_ * vp1 + c_ * vq1;
            __syncthreads();
        }
    }

    // singular values = column norms
    if (t < 64) {
        float s2 = 0.f;
        #pragma unroll 8
        for (int r2 = 0; r2 < 64; r2++) s2 += C[t * 65 + r2] * C[t * 65 + r2];
        sv[t] = sqrtf(s2);
    }
    __syncthreads();
    if (t < 32) {
        float m = fmaxf(sv[t], sv[t + 32]);
        #pragma unroll
        for (int off = 16; off; off >>= 1) m = fmaxf(m, __shfl_xor_sync(0xffffffffu, m, off));
        if (t == 0) smax_s = m;
    }
    __syncthreads();
    float sig = 1.f / (1.f + expf(-(*vp)));
    float tau = sig * 0.4f * smax_s;
    if (t < 64) {
        float si = sv[t];
        wv[t] = (si > tau) ? (si - tau) / si : 0.f;
    }
    __syncthreads();

    // Ltmp[r][u] = sum_c C[r,c] * w_c * V[u,c];  Ptmp = thP + neta*(x - Ltmp)
    float neta = *netap;
    #pragma unroll
    for (int s4 = 0; s4 < 4; s4++) {
        int e = t + 1024 * s4;
        int r2 = e >> 6, u = e & 63;
        float acc = 0.f;
        #pragma unroll 8
        for (int cc = 0; cc < 64; cc++)
            acc += C[cc * 65 + r2] * wv[cc] * V[cc * 65 + u];
        out[e] = acc;
        out[NN + e] = thP[e] + neta * (g_x[e] - acc);
    }
}

// ---------------- launch ----------------
extern "C" void kernel_launch(void* const* d_in, const int* in_sizes, int n_in,
                              void* d_out, int out_size) {
    const float* inp  = (const float*)d_in[0];
    const float* L    = (const float*)d_in[1];
    const void*  mask = (const void*)d_in[2];
    const float* D    = (const float*)d_in[3];
    const float* thP  = (const float*)d_in[4];
    const float* v    = (const float*)d_in[5];
    const float* neta = (const float*)d_in[6];
    const float* l1   = (const float*)d_in[7];
    const float* l2   = (const float*)d_in[8];
    const float* rho  = (const float*)d_in[9];
    const float* S    = (const float*)d_in[10];

    setup_kernel<<<1, 1024>>>(inp, L, mask, thP, D, l1, l2, rho, S);
    for (int k = 0; k < ITERS; k++) {
        if (k == 0) matvec_kernel<true><<<MV_BLOCKS, MV_TPB>>>(D, l1, k);
        else        matvec_kernel<false><<<MV_BLOCKS, MV_TPB>>>(D, l1, k);
    }
    svt_kernel<<<1, 1024>>>(thP, v, neta, (float*)d_out);
}

// round 4
// speedup vs baseline: 1.8289x; 1.8289x over previous
#include <cuda_runtime.h>
#include <cuda_bf16.h>

#define NN 4096
#define ITERS 10
#define SWEEPS 6
#define MV_BLOCKS 128
#define MV_TPB 512

// ---------------- persistent device scratch (static, no runtime alloc) ----------------
__device__ __nv_bfloat16 g_D16[(size_t)NN * NN];   // lamda1 * D_tilda in bf16 (33.5 MB)
__device__ float g_qr[NN];        // q + rho
__device__ float g_Minv[NN];      // Jacobi preconditioner
__device__ float g_StS[64 * 64];  // lamda2 * S^T S
__device__ float g_x[NN], g_r[NN], g_z[NN], g_p[NN], g_Ap[NN];
__device__ float g_zAzA[ITERS], g_zApA[ITERS], g_rzA[ITERS], g_pApA[ITERS];
__device__ int   g_barA[ITERS];

// ---------------- 0) convert: g_D16 = bf16(lamda1 * D)  (DRAM-bound, big grid) -------
__global__ void __launch_bounds__(256) convert_kernel(
    const float* __restrict__ D, const float* __restrict__ l1p)
{
    float l1 = *l1p;
    // 16.7M elements; 2048 blocks x 256 threads; 32 elems/thread as 8x float4
    size_t base = ((size_t)blockIdx.x * 256 + threadIdx.x) * 8;   // float4 index
    const float4* src = (const float4*)D;
    __nv_bfloat162* dst = (__nv_bfloat162*)g_D16;
    float4 v[8];
    #pragma unroll
    for (int i = 0; i < 8; i++) v[i] = src[base + i];
    #pragma unroll
    for (int i = 0; i < 8; i++) {
        __nv_bfloat162 lo, hi;
        lo.x = __float2bfloat16_rn(v[i].x * l1); lo.y = __float2bfloat16_rn(v[i].y * l1);
        hi.x = __float2bfloat16_rn(v[i].z * l1); hi.y = __float2bfloat16_rn(v[i].w * l1);
        dst[(base + i) * 2]     = lo;
        dst[(base + i) * 2 + 1] = hi;
    }
}

// ---------------- 1) setup: StS, b, Minv, CG state, zero reductions/barriers ----------
__global__ void __launch_bounds__(1024) setup_kernel(
    const float* __restrict__ inp, const float* __restrict__ L,
    const void* __restrict__ maskv, const float* __restrict__ thP,
    const float* __restrict__ D,
    const float* __restrict__ l1p, const float* __restrict__ l2p,
    const float* __restrict__ rhop, const float* __restrict__ S)
{
    __shared__ float Ss[64 * 65];
    __shared__ float Ts[64 * 65];
    int t = threadIdx.x;
    float l1 = *l1p, l2 = *l2p, rho = *rhop;

    // detect mask storage: 4-byte words (int32 0/1 or float 0.0/1.0) vs packed bytes
    const unsigned* maskw = (const unsigned*)maskv;
    unsigned wvd = maskw[t];  // t<1024: in-bounds for both layouts
    int bad = (wvd != 0u && wvd != 1u && wvd != 0x3F800000u) ? 1 : 0;
    int bytemode = __syncthreads_or(bad);

    for (int i = t; i < 4096; i += 1024) {
        int h = i >> 6, a = i & 63;
        Ss[h * 65 + a] = S[i];
    }
    __syncthreads();
    for (int e = t; e < 4096; e += 1024) {
        int a = e >> 6, b = e & 63;
        float acc = 0.f;
        #pragma unroll 8
        for (int h = 0; h < 64; h++) acc += Ss[h * 65 + a] * Ss[h * 65 + b];
        acc *= l2;
        Ts[a * 65 + b] = acc;
        g_StS[e] = acc;
    }
    __syncthreads();
    const unsigned char* maskb = (const unsigned char*)maskv;
    for (int n = t; n < NN; n += 1024) {
        float qf;
        if (bytemode) qf = (maskb[n] != 0) ? 1.f : 0.f;
        else          qf = (maskw[n] != 0u) ? 1.f : 0.f;
        float qr = qf + rho;
        g_qr[n] = qr;
        int c = n & 63;
        float dg = D[(size_t)n * (NN + 1)];          // diag(D_tilda)
        float denom = qr + l1 * dg + Ts[c * 65 + c];
        float minv = 1.f / denom;
        g_Minv[n] = minv;
        float bb = rho * (L[n] - thP[n]) + (qf != 0.f ? inp[n] : 0.f);
        g_r[n] = bb;
        g_z[n] = minv * bb;
        g_x[n] = 0.f; g_p[n] = 0.f; g_Ap[n] = 0.f;
    }
    if (t < ITERS) {
        g_zAzA[t] = 0.f; g_zApA[t] = 0.f; g_rzA[t] = 0.f; g_pApA[t] = 0.f;
        g_barA[t] = 0;
    }
}

// ---------------- 2) matvec + fused dots + grid barrier + fused PCG update ------------
// 128 blocks x 512 threads; block owns 32 consecutive rows (all same h); 2 rows/warp.
// Loads explicitly batched (8 independent uint4 in flight) to cover L2/DRAM latency.
__global__ void __launch_bounds__(MV_TPB) matvec_kernel(int k)
{
    __shared__ __align__(16) float zs[NN];   // 16 KB
    __shared__ float Tss[64 * 33];           // 8.4 KB: StS cols u0..u0+31 (scaled)
    __shared__ float az_s[32];
    __shared__ float sred[3];
    int t = threadIdx.x;
    int b = blockIdx.x;
    int row0 = b * 32;
    int h = row0 >> 6;
    int u0 = (b & 1) * 32;
    if (t < 3) sred[t] = 0.f;
    for (int i = t; i < NN; i += MV_TPB) zs[i] = g_z[i];
    for (int i = t; i < 64 * 32; i += MV_TPB) {
        int bb = i >> 5, uu = i & 31;
        Tss[bb * 33 + uu] = g_StS[bb * 64 + u0 + uu];
    }
    __syncthreads();

    int warp = t >> 5, lane = t & 31;
    int r0 = row0 + 2 * warp, r1 = r0 + 1;
    float acc0 = 0.f, acc1 = 0.f;

    const uint4* d0 = (const uint4*)(g_D16 + (size_t)r0 * NN);
    const uint4* d1 = (const uint4*)(g_D16 + (size_t)r1 * NN);
    #pragma unroll
    for (int jo = 0; jo < 4; jo++) {
        uint4 a[4], c[4];
        // batch 8 independent global loads (fills the LSU queue)
        #pragma unroll
        for (int ji = 0; ji < 4; ji++) {
            int idx = lane + 32 * (jo * 4 + ji);
            a[ji] = d0[idx];
            c[ji] = d1[idx];
        }
        #pragma unroll
        for (int ji = 0; ji < 4; ji++) {
            int idx = lane + 32 * (jo * 4 + ji);
            float4 za = ((const float4*)zs)[2 * idx];
            float4 zb = ((const float4*)zs)[2 * idx + 1];
            float2 p0 = __bfloat1622float2(*(__nv_bfloat162*)&a[ji].x);
            float2 p1 = __bfloat1622float2(*(__nv_bfloat162*)&a[ji].y);
            float2 p2 = __bfloat1622float2(*(__nv_bfloat162*)&a[ji].z);
            float2 p3 = __bfloat1622float2(*(__nv_bfloat162*)&a[ji].w);
            acc0 += p0.x * za.x + p0.y * za.y + p1.x * za.z + p1.y * za.w
                  + p2.x * zb.x + p2.y * zb.y + p3.x * zb.z + p3.y * zb.w;
            p0 = __bfloat1622float2(*(__nv_bfloat162*)&c[ji].x);
            p1 = __bfloat1622float2(*(__nv_bfloat162*)&c[ji].y);
            p2 = __bfloat1622float2(*(__nv_bfloat162*)&c[ji].z);
            p3 = __bfloat1622float2(*(__nv_bfloat162*)&c[ji].w);
            acc1 += p0.x * za.x + p0.y * za.y + p1.x * za.z + p1.y * za.w
                  + p2.x * zb.x + p2.y * zb.y + p3.x * zb.z + p3.y * zb.w;
        }
    }

    // lamda2 * (Z @ StS) term: row n=(h,u) needs sum_b StS[b][u]*z[h*64+b]
    {
        int uu0 = (r0 & 63) - u0;
        int uu1 = uu0 + 1;
        float zl = zs[(h << 6) + lane];
        float zh2 = zs[(h << 6) + lane + 32];
        acc0 += Tss[lane * 33 + uu0] * zl + Tss[(lane + 32) * 33 + uu0] * zh2;
        acc1 += Tss[lane * 33 + uu1] * zl + Tss[(lane + 32) * 33 + uu1] * zh2;
    }
    #pragma unroll
    for (int off = 16; off; off >>= 1) {
        acc0 += __shfl_xor_sync(0xffffffffu, acc0, off);
        acc1 += __shfl_xor_sync(0xffffffffu, acc1, off);
    }
    if (lane < 2) {
        int row = r0 + lane;
        float a = lane ? acc1 : acc0;
        float zr = zs[row];
        float Azv = a + g_qr[row] * zr;
        az_s[2 * warp + lane] = Azv;
        atomicAdd(&sred[0], zr * Azv);         // z'Az
        atomicAdd(&sred[1], zr * g_Ap[row]);   // z'Ap_old
        atomicAdd(&sred[2], g_r[row] * zr);    // r'z
    }
    __syncthreads();

    // software grid barrier (128 co-resident blocks)
    if (t == 0) {
        atomicAdd(&g_zAzA[k], sred[0]);
        atomicAdd(&g_zApA[k], sred[1]);
        atomicAdd(&g_rzA[k],  sred[2]);
        __threadfence();
        atomicAdd(&g_barA[k], 1);
        while (*(volatile int*)&g_barA[k] < MV_BLOCKS) __nanosleep(128);
    }
    __syncthreads();

    // fused PCG update for OWN 32 rows
    if (t < 32) {
        float zAz = *(volatile float*)&g_zAzA[k];
        float zAp = *(volatile float*)&g_zApA[k];
        float rz  = *(volatile float*)&g_rzA[k];
        float beta = 0.f, pApprev = 0.f;
        if (k > 0) {
            float rzp = g_rzA[k - 1];     // finalized in previous launch
            beta = (rzp != 0.f) ? rz / rzp : 0.f;
            pApprev = g_pApA[k - 1];
        }
        float pAp = zAz + 2.f * beta * zAp + beta * beta * pApprev;
        float alpha = (pAp != 0.f) ? rz / pAp : 0.f;
        int row = row0 + t;
        float zn = zs[row];
        float pn = zn + beta * g_p[row];
        float Apn = az_s[t] + beta * g_Ap[row];
        g_p[row] = pn; g_Ap[row] = Apn;
        g_x[row] = g_x[row] + alpha * pn;
        float rn = g_r[row] - alpha * Apn;
        g_r[row] = rn;
        g_z[row] = g_Minv[row] * rn;
        if (t == 0 && b == 0) g_pApA[k] = pAp;
    }
}

// ---------------- 3) SVT via TWO-SIDED Jacobi eig of B = M^T M  (single block) --------
// Rotation params come from 3 smem scalar reads (no per-round dot products / shfl
// reductions — those were the R3 regression).
__global__ void __launch_bounds__(1024) svt_kernel(
    const float* __restrict__ thP, const float* __restrict__ vp,
    const float* __restrict__ netap, float* __restrict__ out)
{
    __shared__ float A1[64 * 65];  // M, then V, then M again
    __shared__ float A2[64 * 65];  // B, then W
    __shared__ float sv[64], wv[64];
    __shared__ float smax_s;
    int t = threadIdx.x, warp = t >> 5, lane = t & 31;

    // M = x + th_P
    for (int n = t; n < NN; n += 1024)
        A1[(n >> 6) * 65 + (n & 63)] = g_x[n] + thP[n];
    __syncthreads();
    // B = M^T M
    #pragma unroll
    for (int s4 = 0; s4 < 4; s4++) {
        int e = t + 1024 * s4;
        int i = e >> 6, j = e & 63;
        float acc = 0.f;
        #pragma unroll 8
        for (int kk = 0; kk < 64; kk++) acc += A1[kk * 65 + i] * A1[kk * 65 + j];
        A2[i * 65 + j] = acc;
    }
    __syncthreads();
    // V = I (overwrites M)
    for (int n = t; n < 64 * 65; n += 1024) A1[n] = 0.f;
    __syncthreads();
    if (t < 64) A1[t * 65 + t] = 1.f;
    __syncthreads();

    // parallel cyclic Jacobi: 32 disjoint pairs per round (round-robin tournament)
    for (int sw = 0; sw < SWEEPS; sw++) {
        for (int r = 0; r < 63; r++) {
            int j1 = warp, j2 = 63 - warp;
            int p = (j1 == 0) ? 0 : (1 + ((j1 - 1 + r) % 63));
            int q = 1 + ((j2 - 1 + r) % 63);
            float c = 1.f, s = 0.f;
            if (lane == 0) {
                float app = A2[p * 65 + p], aqq = A2[q * 65 + q], apq = A2[p * 65 + q];
                if (fabsf(apq) > 0.f) {
                    float theta = (aqq - app) / (2.f * apq);
                    float tt = 1.f / (fabsf(theta) + sqrtf(theta * theta + 1.f));
                    if (theta < 0.f) tt = -tt;
                    c = rsqrtf(1.f + tt * tt);
                    s = tt * c;
                }
            }
            c = __shfl_sync(0xffffffffu, c, 0);
            s = __shfl_sync(0xffffffffu, s, 0);
            // row phase: rows p,q (disjoint across warps)
            {
                int k1 = lane, k2 = lane + 32;
                float bp = A2[p * 65 + k1], bq = A2[q * 65 + k1];
                A2[p * 65 + k1] = c * bp - s * bq;
                A2[q * 65 + k1] = s * bp + c * bq;
                bp = A2[p * 65 + k2]; bq = A2[q * 65 + k2];
                A2[p * 65 + k2] = c * bp - s * bq;
                A2[q * 65 + k2] = s * bp + c * bq;
            }
            __syncthreads();
            // col phase (B and V): cols p,q (disjoint across warps)
            {
                int k1 = lane, k2 = lane + 32;
                float bp = A2[k1 * 65 + p], bq = A2[k1 * 65 + q];
                A2[k1 * 65 + p] = c * bp - s * bq;
                A2[k1 * 65 + q] = s * bp + c * bq;
                bp = A2[k2 * 65 + p]; bq = A2[k2 * 65 + q];
                A2[k2 * 65 + p] = c * bp - s * bq;
                A2[k2 * 65 + q] = s * bp + c * bq;
                float vx = A1[k1 * 65 + p], vy = A1[k1 * 65 + q];
                A1[k1 * 65 + p] = c * vx - s * vy;
                A1[k1 * 65 + q] = s * vx + c * vy;
                vx = A1[k2 * 65 + p]; vy = A1[k2 * 65 + q];
                A1[k2 * 65 + p] = c * vx - s * vy;
                A1[k2 * 65 + q] = s * vx + c * vy;
            }
            __syncthreads();
        }
    }

    // singular values, threshold weights
    if (t < 64) sv[t] = sqrtf(fmaxf(A2[t * 65 + t], 0.f));
    __syncthreads();
    if (t < 32) {
        float m = fmaxf(sv[t], sv[t + 32]);
        #pragma unroll
        for (int off = 16; off; off >>= 1) m = fmaxf(m, __shfl_xor_sync(0xffffffffu, m, off));
        if (t == 0) smax_s = m;
    }
    __syncthreads();
    float vscal = *vp;
    float sig = 1.f / (1.f + expf(-vscal));
    float tau_abs = sig * 0.4f * smax_s;
    if (t < 64) {
        float si = sv[t];
        wv[t] = (si > tau_abs) ? (si - tau_abs) / si : 0.f;
    }
    __syncthreads();
    // W = V diag(w) V^T  -> A2
    #pragma unroll
    for (int s4 = 0; s4 < 4; s4++) {
        int e = t + 1024 * s4;
        int i = e >> 6, j = e & 63;
        float acc = 0.f;
        #pragma unroll 8
        for (int kk = 0; kk < 64; kk++) acc += A1[i * 65 + kk] * wv[kk] * A1[j * 65 + kk];
        A2[i * 65 + j] = acc;
    }
    __syncthreads();
    // reload M -> A1
    for (int n = t; n < NN; n += 1024)
        A1[(n >> 6) * 65 + (n & 63)] = g_x[n] + thP[n];
    __syncthreads();
    // Ltmp = M @ W ; Ptmp = th_P + neta*(x - Ltmp)
    float neta = *netap;
    #pragma unroll
    for (int s4 = 0; s4 < 4; s4++) {
        int e = t + 1024 * s4;
        int h = e >> 6, u = e & 63;
        float acc = 0.f;
        #pragma unroll 8
        for (int kk = 0; kk < 64; kk++) acc += A1[h * 65 + kk] * A2[kk * 65 + u];
        out[e] = acc;
        out[NN + e] = thP[e] + neta * (g_x[e] - acc);
    }
}

// ---------------- launch ----------------
extern "C" void kernel_launch(void* const* d_in, const int* in_sizes, int n_in,
                              void* d_out, int out_size) {
    const float* inp  = (const float*)d_in[0];
    const float* L    = (const float*)d_in[1];
    const void*  mask = (const void*)d_in[2];
    const float* D    = (const float*)d_in[3];
    const float* thP  = (const float*)d_in[4];
    const float* v    = (const float*)d_in[5];
    const float* neta = (const float*)d_in[6];
    const float* l1   = (const float*)d_in[7];
    const float* l2   = (const float*)d_in[8];
    const float* rho  = (const float*)d_in[9];
    const float* S    = (const float*)d_in[10];

    convert_kernel<<<2048, 256>>>(D, l1);
    setup_kernel<<<1, 1024>>>(inp, L, mask, thP, D, l1, l2, rho, S);
    for (int k = 0; k < ITERS; k++)
        matvec_kernel<<<MV_BLOCKS, MV_TPB>>>(k);
    svt_kernel<<<1, 1024>>>(thP, v, neta, (float*)d_out);
}

// round 5
// speedup vs baseline: 1.8387x; 1.0053x over previous
#include <cuda_runtime.h>
#include <cuda_bf16.h>
#include <cuda_pipeline.h>

#define NN 4096
#define ITERS 10
#define SWEEPS 6
#define MV_BLOCKS 128
#define MV_TPB 512
#define NCHUNK 16
#define ROW_CB 512                      // bytes per row per chunk (256 bf16)
#define CHUNK_B (32 * ROW_CB)           // 16 KB per chunk stage
#define SMEM_CG (25088 + 3 * CHUNK_B)   // 74240 bytes

// ---------------- persistent device scratch (static, no runtime alloc) ----------------
__device__ __nv_bfloat16 g_D16[(size_t)NN * NN];   // lamda1 * D_tilda in bf16 (33.5 MB)
__device__ float g_qr[NN];        // q + rho
__device__ float g_Minv[NN];      // Jacobi preconditioner
__device__ float g_StS[64 * 64];  // lamda2 * S^T S
__device__ float g_x[NN], g_r[NN], g_z[NN], g_p[NN], g_Ap[NN];
__device__ float g_zAzA[ITERS], g_zApA[ITERS], g_rzA[ITERS];
__device__ int   g_barA[2 * ITERS];

// ---------------- 0) convert: g_D16 = bf16(lamda1 * D)  (DRAM-bound, big grid) -------
__global__ void __launch_bounds__(256) convert_kernel(
    const float* __restrict__ D, const float* __restrict__ l1p)
{
    float l1 = *l1p;
    size_t base = ((size_t)blockIdx.x * 256 + threadIdx.x) * 8;   // float4 index
    const float4* src = (const float4*)D;
    __nv_bfloat162* dst = (__nv_bfloat162*)g_D16;
    float4 v[8];
    #pragma unroll
    for (int i = 0; i < 8; i++) v[i] = src[base + i];
    #pragma unroll
    for (int i = 0; i < 8; i++) {
        __nv_bfloat162 lo, hi;
        lo.x = __float2bfloat16_rn(v[i].x * l1); lo.y = __float2bfloat16_rn(v[i].y * l1);
        hi.x = __float2bfloat16_rn(v[i].z * l1); hi.y = __float2bfloat16_rn(v[i].w * l1);
        dst[(base + i) * 2]     = lo;
        dst[(base + i) * 2 + 1] = hi;
    }
}

// ---------------- 1) setup: StS, b, Minv, CG state, zero reductions/barriers ----------
__global__ void __launch_bounds__(1024) setup_kernel(
    const float* __restrict__ inp, const float* __restrict__ L,
    const void* __restrict__ maskv, const float* __restrict__ thP,
    const float* __restrict__ D,
    const float* __restrict__ l1p, const float* __restrict__ l2p,
    const float* __restrict__ rhop, const float* __restrict__ S)
{
    __shared__ float Ss[64 * 65];
    __shared__ float Ts[64 * 65];
    int t = threadIdx.x;
    float l1 = *l1p, l2 = *l2p, rho = *rhop;

    // detect mask storage: 4-byte words (int32 0/1 or float 0.0/1.0) vs packed bytes
    const unsigned* maskw = (const unsigned*)maskv;
    unsigned wvd = maskw[t];
    int bad = (wvd != 0u && wvd != 1u && wvd != 0x3F800000u) ? 1 : 0;
    int bytemode = __syncthreads_or(bad);

    for (int i = t; i < 4096; i += 1024) {
        int h = i >> 6, a = i & 63;
        Ss[h * 65 + a] = S[i];
    }
    __syncthreads();
    for (int e = t; e < 4096; e += 1024) {
        int a = e >> 6, b = e & 63;
        float acc = 0.f;
        #pragma unroll 8
        for (int h = 0; h < 64; h++) acc += Ss[h * 65 + a] * Ss[h * 65 + b];
        acc *= l2;
        Ts[a * 65 + b] = acc;
        g_StS[e] = acc;
    }
    __syncthreads();
    const unsigned char* maskb = (const unsigned char*)maskv;
    for (int n = t; n < NN; n += 1024) {
        float qf;
        if (bytemode) qf = (maskb[n] != 0) ? 1.f : 0.f;
        else          qf = (maskw[n] != 0u) ? 1.f : 0.f;
        float qr = qf + rho;
        g_qr[n] = qr;
        int c = n & 63;
        float dg = D[(size_t)n * (NN + 1)];
        float denom = qr + l1 * dg + Ts[c * 65 + c];
        float minv = 1.f / denom;
        g_Minv[n] = minv;
        float bb = rho * (L[n] - thP[n]) + (qf != 0.f ? inp[n] : 0.f);
        g_r[n] = bb;
        g_z[n] = minv * bb;
        g_x[n] = 0.f; g_p[n] = 0.f; g_Ap[n] = 0.f;
    }
    if (t < ITERS) { g_zAzA[t] = 0.f; g_zApA[t] = 0.f; g_rzA[t] = 0.f; }
    if (t < 2 * ITERS) g_barA[t] = 0;
}

// ---------------- 2) PERSISTENT CG: all iterations in one kernel ---------------------
// 128 blocks x 512 threads; block owns 32 rows; 2 rows/warp.
// D rows streamed via 3-stage cp.async pipeline (LDGSTS: no register pressure -> MLP).
// Cross-block data (g_z, scalar sums) read via L1-bypassing loads (persistent kernel!).
__global__ void __launch_bounds__(MV_TPB) cg_kernel()
{
    extern __shared__ __align__(16) char sm[];
    float* zs   = (float*)sm;                       // [0, 16384)
    float* Tss  = (float*)(sm + 16384);             // [16384, 24832): 64*33
    float* az_s = (float*)(sm + 24832);             // 32 floats
    float* sred = (float*)(sm + 24960);             // 3 floats
    __nv_bfloat16* stage = (__nv_bfloat16*)(sm + 25088);  // 3 x 16KB

    int t = threadIdx.x, b = blockIdx.x;
    int row0 = b * 32;
    int h = row0 >> 6;
    int u0 = (b & 1) * 32;
    int warp = t >> 5, lane = t & 31;
    int r0 = row0 + 2 * warp;

    // StS tile (cols u0..u0+31), loaded once
    for (int i = t; i < 64 * 32; i += MV_TPB) {
        int bb = i >> 5, uu = i & 31;
        Tss[bb * 33 + uu] = g_StS[bb * 64 + u0 + uu];
    }

    // this thread's cp.async slice: row lrow (0..31), 32 bytes at loff
    int lrow = t >> 4;
    int loff = (t & 15) * 32;
    const char* srow = (const char*)(g_D16 + (size_t)(row0 + lrow) * NN);

    float rz_prev = 0.f, pAp_prev = 0.f;

    for (int k = 0; k < ITERS; k++) {
        if (t < 3) sred[t] = 0.f;
        // z broadcast: MUST bypass L1 (other SMs wrote g_z since our last read)
        for (int i = t; i < NN; i += MV_TPB) zs[i] = __ldcg(&g_z[i]);

        // prologue: issue chunks 0,1
        #pragma unroll
        for (int c = 0; c < 2; c++) {
            char* d = (char*)stage + (c % 3) * CHUNK_B + lrow * ROW_CB + loff;
            const char* s = srow + c * ROW_CB + loff;
            __pipeline_memcpy_async(d, s, 16);
            __pipeline_memcpy_async(d + 16, s + 16, 16);
            __pipeline_commit();
        }
        __syncthreads();   // zs (+ Tss on first iter) ready

        float acc0 = 0.f, acc1 = 0.f;
        #pragma unroll
        for (int c = 0; c < NCHUNK; c++) {
            if (c < NCHUNK - 1) __pipeline_wait_prior(1);
            else                __pipeline_wait_prior(0);
            __syncthreads();   // whole chunk visible to all threads
            const char* st = (const char*)stage + (c % 3) * CHUNK_B;
            uint4 d0 = *(const uint4*)(st + (2 * warp) * ROW_CB + lane * 16);
            uint4 d1 = *(const uint4*)(st + (2 * warp + 1) * ROW_CB + lane * 16);
            float4 za = *(const float4*)(zs + c * 256 + lane * 8);
            float4 zb = *(const float4*)(zs + c * 256 + lane * 8 + 4);
            float2 p0 = __bfloat1622float2(*(__nv_bfloat162*)&d0.x);
            float2 p1 = __bfloat1622float2(*(__nv_bfloat162*)&d0.y);
            float2 p2 = __bfloat1622float2(*(__nv_bfloat162*)&d0.z);
            float2 p3 = __bfloat1622float2(*(__nv_bfloat162*)&d0.w);
            acc0 += p0.x * za.x + p0.y * za.y + p1.x * za.z + p1.y * za.w
                  + p2.x * zb.x + p2.y * zb.y + p3.x * zb.z + p3.y * zb.w;
            p0 = __bfloat1622float2(*(__nv_bfloat162*)&d1.x);
            p1 = __bfloat1622float2(*(__nv_bfloat162*)&d1.y);
            p2 = __bfloat1622float2(*(__nv_bfloat162*)&d1.z);
            p3 = __bfloat1622float2(*(__nv_bfloat162*)&d1.w);
            acc1 += p0.x * za.x + p0.y * za.y + p1.x * za.z + p1.y * za.w
                  + p2.x * zb.x + p2.y * zb.y + p3.x * zb.z + p3.y * zb.w;
            // issue chunk c+2 into stage just freed at chunk c-1 (safe: all threads
            // passed this chunk's __syncthreads => finished compute of c-1)
            if (c + 2 < NCHUNK) {
                int cc = c + 2;
                char* d = (char*)stage + (cc % 3) * CHUNK_B + lrow * ROW_CB + loff;
                const char* s = srow + cc * ROW_CB + loff;
                __pipeline_memcpy_async(d, s, 16);
                __pipeline_memcpy_async(d + 16, s + 16, 16);
                __pipeline_commit();
            }
        }

        // lamda2 * (Z @ StS) term: row n=(h,u) needs sum_b StS[b][u]*z[h*64+b]
        {
            int uu0 = (r0 & 63) - u0;
            int uu1 = uu0 + 1;
            float zl  = zs[(h << 6) + lane];
            float zh2 = zs[(h << 6) + lane + 32];
            acc0 += Tss[lane * 33 + uu0] * zl + Tss[(lane + 32) * 33 + uu0] * zh2;
            acc1 += Tss[lane * 33 + uu1] * zl + Tss[(lane + 32) * 33 + uu1] * zh2;
        }
        #pragma unroll
        for (int off = 16; off; off >>= 1) {
            acc0 += __shfl_xor_sync(0xffffffffu, acc0, off);
            acc1 += __shfl_xor_sync(0xffffffffu, acc1, off);
        }
        if (lane < 2) {
            int row = r0 + lane;
            float a = lane ? acc1 : acc0;
            float zr = zs[row];
            float Azv = a + g_qr[row] * zr;        // own rows: same-SM data, L1 fine
            az_s[2 * warp + lane] = Azv;
            atomicAdd(&sred[0], zr * Azv);         // z'Az
            atomicAdd(&sred[1], zr * g_Ap[row]);   // z'Ap_old (own rows)
            atomicAdd(&sred[2], g_r[row] * zr);    // r'z (own rows)
        }
        __syncthreads();

        // grid barrier A: publish partial dots
        if (t == 0) {
            atomicAdd(&g_zAzA[k], sred[0]);
            atomicAdd(&g_zApA[k], sred[1]);
            atomicAdd(&g_rzA[k],  sred[2]);
            __threadfence();
            atomicAdd(&g_barA[2 * k], 1);
            while (*(volatile int*)&g_barA[2 * k] < MV_BLOCKS) __nanosleep(64);
        }
        __syncthreads();

        // scalars (identical in every thread; history carried in registers)
        float zAz = *(volatile float*)&g_zAzA[k];
        float zAp = *(volatile float*)&g_zApA[k];
        float rz  = *(volatile float*)&g_rzA[k];
        float beta = (k > 0 && rz_prev != 0.f) ? rz / rz_prev : 0.f;
        float pAp = zAz + 2.f * beta * zAp + beta * beta * pAp_prev;
        float alpha = (pAp != 0.f) ? rz / pAp : 0.f;
        rz_prev = rz; pAp_prev = pAp;

        // PCG update of OWN 32 rows
        if (t < 32) {
            int row = row0 + t;
            float zn = zs[row];
            float pn = zn + beta * g_p[row];
            float Apn = az_s[t] + beta * g_Ap[row];
            g_p[row] = pn; g_Ap[row] = Apn;
            g_x[row] = g_x[row] + alpha * pn;
            float rn = g_r[row] - alpha * Apn;
            g_r[row] = rn;
            g_z[row] = g_Minv[row] * rn;
            __threadfence();                       // publish z before barrier B
        }
        __syncthreads();

        // grid barrier B: everyone's z update visible before next iteration
        if (t == 0) {
            atomicAdd(&g_barA[2 * k + 1], 1);
            while (*(volatile int*)&g_barA[2 * k + 1] < MV_BLOCKS) __nanosleep(64);
        }
        __syncthreads();
    }
}

// ---------------- 3) SVT via TWO-SIDED Jacobi eig of B = M^T M  (single block) --------
__global__ void __launch_bounds__(1024) svt_kernel(
    const float* __restrict__ thP, const float* __restrict__ vp,
    const float* __restrict__ netap, float* __restrict__ out)
{
    __shared__ float A1[64 * 65];  // M, then V, then M again
    __shared__ float A2[64 * 65];  // B, then W
    __shared__ float sv[64], wv[64];
    __shared__ float smax_s;
    int t = threadIdx.x, warp = t >> 5, lane = t & 31;

    for (int n = t; n < NN; n += 1024)
        A1[(n >> 6) * 65 + (n & 63)] = g_x[n] + thP[n];
    __syncthreads();
    #pragma unroll
    for (int s4 = 0; s4 < 4; s4++) {
        int e = t + 1024 * s4;
        int i = e >> 6, j = e & 63;
        float acc = 0.f;
        #pragma unroll 8
        for (int kk = 0; kk < 64; kk++) acc += A1[kk * 65 + i] * A1[kk * 65 + j];
        A2[i * 65 + j] = acc;
    }
    __syncthreads();
    for (int n = t; n < 64 * 65; n += 1024) A1[n] = 0.f;
    __syncthreads();
    if (t < 64) A1[t * 65 + t] = 1.f;
    __syncthreads();

    for (int sw = 0; sw < SWEEPS; sw++) {
        for (int r = 0; r < 63; r++) {
            int j1 = warp, j2 = 63 - warp;
            int p = (j1 == 0) ? 0 : (1 + ((j1 - 1 + r) % 63));
            int q = 1 + ((j2 - 1 + r) % 63);
            float c = 1.f, s = 0.f;
            if (lane == 0) {
                float app = A2[p * 65 + p], aqq = A2[q * 65 + q], apq = A2[p * 65 + q];
                if (fabsf(apq) > 0.f) {
                    float theta = (aqq - app) / (2.f * apq);
                    float tt = 1.f / (fabsf(theta) + sqrtf(theta * theta + 1.f));
                    if (theta < 0.f) tt = -tt;
                    c = rsqrtf(1.f + tt * tt);
                    s = tt * c;
                }
            }
            c = __shfl_sync(0xffffffffu, c, 0);
            s = __shfl_sync(0xffffffffu, s, 0);
            {
                int k1 = lane, k2 = lane + 32;
                float bp = A2[p * 65 + k1], bq = A2[q * 65 + k1];
                A2[p * 65 + k1] = c * bp - s * bq;
                A2[q * 65 + k1] = s * bp + c * bq;
                bp = A2[p * 65 + k2]; bq = A2[q * 65 + k2];
                A2[p * 65 + k2] = c * bp - s * bq;
                A2[q * 65 + k2] = s * bp + c * bq;
            }
            __syncthreads();
            {
                int k1 = lane, k2 = lane + 32;
                float bp = A2[k1 * 65 + p], bq = A2[k1 * 65 + q];
                A2[k1 * 65 + p] = c * bp - s * bq;
                A2[k1 * 65 + q] = s * bp + c * bq;
                bp = A2[k2 * 65 + p]; bq = A2[k2 * 65 + q];
                A2[k2 * 65 + p] = c * bp - s * bq;
                A2[k2 * 65 + q] = s * bp + c * bq;
                float vx = A1[k1 * 65 + p], vy = A1[k1 * 65 + q];
                A1[k1 * 65 + p] = c * vx - s * vy;
                A1[k1 * 65 + q] = s * vx + c * vy;
                vx = A1[k2 * 65 + p]; vy = A1[k2 * 65 + q];
                A1[k2 * 65 + p] = c * vx - s * vy;
                A1[k2 * 65 + q] = s * vx + c * vy;
            }
            __syncthreads();
        }
    }

    if (t < 64) sv[t] = sqrtf(fmaxf(A2[t * 65 + t], 0.f));
    __syncthreads();
    if (t < 32) {
        float m = fmaxf(sv[t], sv[t + 32]);
        #pragma unroll
        for (int off = 16; off; off >>= 1) m = fmaxf(m, __shfl_xor_sync(0xffffffffu, m, off));
        if (t == 0) smax_s = m;
    }
    __syncthreads();
    float sig = 1.f / (1.f + expf(-(*vp)));
    float tau_abs = sig * 0.4f * smax_s;
    if (t < 64) {
        float si = sv[t];
        wv[t] = (si > tau_abs) ? (si - tau_abs) / si : 0.f;
    }
    __syncthreads();
    #pragma unroll
    for (int s4 = 0; s4 < 4; s4++) {
        int e = t + 1024 * s4;
        int i = e >> 6, j = e & 63;
        float acc = 0.f;
        #pragma unroll 8
        for (int kk = 0; kk < 64; kk++) acc += A1[i * 65 + kk] * wv[kk] * A1[j * 65 + kk];
        A2[i * 65 + j] = acc;
    }
    __syncthreads();
    for (int n = t; n < NN; n += 1024)
        A1[(n >> 6) * 65 + (n & 63)] = g_x[n] + thP[n];
    __syncthreads();
    float neta = *netap;
    #pragma unroll
    for (int s4 = 0; s4 < 4; s4++) {
        int e = t + 1024 * s4;
        int hh = e >> 6, u = e & 63;
        float acc = 0.f;
        #pragma unroll 8
        for (int kk = 0; kk < 64; kk++) acc += A1[hh * 65 + kk] * A2[kk * 65 + u];
        out[e] = acc;
        out[NN + e] = thP[e] + neta * (g_x[e] - acc);
    }
}

// ---------------- launch ----------------
extern "C" void kernel_launch(void* const* d_in, const int* in_sizes, int n_in,
                              void* d_out, int out_size) {
    const float* inp  = (const float*)d_in[0];
    const float* L    = (const float*)d_in[1];
    const void*  mask = (const void*)d_in[2];
    const float* D    = (const float*)d_in[3];
    const float* thP  = (const float*)d_in[4];
    const float* v    = (const float*)d_in[5];
    const float* neta = (const float*)d_in[6];
    const float* l1   = (const float*)d_in[7];
    const float* l2   = (const float*)d_in[8];
    const float* rho  = (const float*)d_in[9];
    const float* S    = (const float*)d_in[10];

    cudaFuncSetAttribute(cg_kernel, cudaFuncAttributeMaxDynamicSharedMemorySize, SMEM_CG);

    convert_kernel<<<2048, 256>>>(D, l1);
    setup_kernel<<<1, 1024>>>(inp, L, mask, thP, D, l1, l2, rho, S);
    cg_kernel<<<MV_BLOCKS, MV_TPB, SMEM_CG>>>();
    svt_kernel<<<1, 1024>>>(thP, v, neta, (float*)d_out);
}

// round 6
// speedup vs baseline: 2.2420x; 1.2193x over previous
#include <cuda_runtime.h>
#include <cuda_bf16.h>
#include <cuda_pipeline.h>

#define NN 4096
#define ITERS 10
#define SWEEPS 6
#define MV_BLOCKS 128
#define MV_TPB 512
#define NCHUNK 16
#define ROW_CB 512                      // bytes per row per chunk (256 bf16)
#define CHUNK_B (32 * ROW_CB)           // 16 KB per chunk stage
#define SMEM_CG (25088 + 3 * CHUNK_B)   // 74240 bytes

// ---------------- persistent device scratch (static, no runtime alloc) ----------------
__device__ __nv_bfloat16 g_D16[(size_t)NN * NN];   // lamda1 * D_tilda in bf16 (33.5 MB)
__device__ float g_qr[NN];        // q + rho
__device__ float g_Minv[NN];      // Jacobi preconditioner
__device__ float g_StS[64 * 64];  // lamda2 * S^T S
__device__ float g_x[NN], g_r[NN], g_z[NN], g_p[NN], g_Ap[NN];
__device__ float g_zAzA[ITERS], g_zApA[ITERS], g_rzA[ITERS];
__device__ int   g_barA[2 * ITERS];

// ---------------- 0) convert: g_D16 = bf16(lamda1 * D)  (DRAM-bound, big grid) -------
__global__ void __launch_bounds__(256) convert_kernel(
    const float* __restrict__ D, const float* __restrict__ l1p)
{
    float l1 = *l1p;
    size_t base = ((size_t)blockIdx.x * 256 + threadIdx.x) * 8;   // float4 index
    const float4* src = (const float4*)D;
    __nv_bfloat162* dst = (__nv_bfloat162*)g_D16;
    float4 v[8];
    #pragma unroll
    for (int i = 0; i < 8; i++) v[i] = src[base + i];
    #pragma unroll
    for (int i = 0; i < 8; i++) {
        __nv_bfloat162 lo, hi;
        lo.x = __float2bfloat16_rn(v[i].x * l1); lo.y = __float2bfloat16_rn(v[i].y * l1);
        hi.x = __float2bfloat16_rn(v[i].z * l1); hi.y = __float2bfloat16_rn(v[i].w * l1);
        dst[(base + i) * 2]     = lo;
        dst[(base + i) * 2 + 1] = hi;
    }
}

// ---------------- 1) setup: StS, b, Minv, CG state, zero reductions/barriers ----------
__global__ void __launch_bounds__(1024) setup_kernel(
    const float* __restrict__ inp, const float* __restrict__ L,
    const void* __restrict__ maskv, const float* __restrict__ thP,
    const float* __restrict__ D,
    const float* __restrict__ l1p, const float* __restrict__ l2p,
    const float* __restrict__ rhop, const float* __restrict__ S)
{
    __shared__ float Ss[64 * 65];
    __shared__ float Ts[64 * 65];
    int t = threadIdx.x;
    float l1 = *l1p, l2 = *l2p, rho = *rhop;

    // detect mask storage: 4-byte words (int32 0/1 or float 0.0/1.0) vs packed bytes
    const unsigned* maskw = (const unsigned*)maskv;
    unsigned wvd = maskw[t];
    int bad = (wvd != 0u && wvd != 1u && wvd != 0x3F800000u) ? 1 : 0;
    int bytemode = __syncthreads_or(bad);

    for (int i = t; i < 4096; i += 1024) {
        int h = i >> 6, a = i & 63;
        Ss[h * 65 + a] = S[i];
    }
    __syncthreads();
    for (int e = t; e < 4096; e += 1024) {
        int a = e >> 6, b = e & 63;
        float acc = 0.f;
        #pragma unroll 8
        for (int h = 0; h < 64; h++) acc += Ss[h * 65 + a] * Ss[h * 65 + b];
        acc *= l2;
        Ts[a * 65 + b] = acc;
        g_StS[e] = acc;
    }
    __syncthreads();
    const unsigned char* maskb = (const unsigned char*)maskv;
    for (int n = t; n < NN; n += 1024) {
        float qf;
        if (bytemode) qf = (maskb[n] != 0) ? 1.f : 0.f;
        else          qf = (maskw[n] != 0u) ? 1.f : 0.f;
        float qr = qf + rho;
        g_qr[n] = qr;
        int c = n & 63;
        float dg = D[(size_t)n * (NN + 1)];
        float denom = qr + l1 * dg + Ts[c * 65 + c];
        float minv = 1.f / denom;
        g_Minv[n] = minv;
        float bb = rho * (L[n] - thP[n]) + (qf != 0.f ? inp[n] : 0.f);
        g_r[n] = bb;
        g_z[n] = minv * bb;
        g_x[n] = 0.f; g_p[n] = 0.f; g_Ap[n] = 0.f;
    }
    if (t < ITERS) { g_zAzA[t] = 0.f; g_zApA[t] = 0.f; g_rzA[t] = 0.f; }
    if (t < 2 * ITERS) g_barA[t] = 0;
}

// ---------------- 2) PERSISTENT CG: all iterations in one kernel ---------------------
__global__ void __launch_bounds__(MV_TPB) cg_kernel()
{
    extern __shared__ __align__(16) char sm[];
    float* zs   = (float*)sm;                       // [0, 16384)
    float* Tss  = (float*)(sm + 16384);             // [16384, 24832): 64*33
    float* az_s = (float*)(sm + 24832);             // 32 floats
    float* sred = (float*)(sm + 24960);             // 3 floats
    __nv_bfloat16* stage = (__nv_bfloat16*)(sm + 25088);  // 3 x 16KB

    int t = threadIdx.x, b = blockIdx.x;
    int row0 = b * 32;
    int h = row0 >> 6;
    int u0 = (b & 1) * 32;
    int warp = t >> 5, lane = t & 31;
    int r0 = row0 + 2 * warp;

    for (int i = t; i < 64 * 32; i += MV_TPB) {
        int bb = i >> 5, uu = i & 31;
        Tss[bb * 33 + uu] = g_StS[bb * 64 + u0 + uu];
    }

    int lrow = t >> 4;
    int loff = (t & 15) * 32;
    const char* srow = (const char*)(g_D16 + (size_t)(row0 + lrow) * NN);

    float rz_prev = 0.f, pAp_prev = 0.f;

    for (int k = 0; k < ITERS; k++) {
        if (t < 3) sred[t] = 0.f;
        for (int i = t; i < NN; i += MV_TPB) zs[i] = __ldcg(&g_z[i]);

        #pragma unroll
        for (int c = 0; c < 2; c++) {
            char* d = (char*)stage + (c % 3) * CHUNK_B + lrow * ROW_CB + loff;
            const char* s = srow + c * ROW_CB + loff;
            __pipeline_memcpy_async(d, s, 16);
            __pipeline_memcpy_async(d + 16, s + 16, 16);
            __pipeline_commit();
        }
        __syncthreads();

        float acc0 = 0.f, acc1 = 0.f;
        #pragma unroll
        for (int c = 0; c < NCHUNK; c++) {
            if (c < NCHUNK - 1) __pipeline_wait_prior(1);
            else                __pipeline_wait_prior(0);
            __syncthreads();
            const char* st = (const char*)stage + (c % 3) * CHUNK_B;
            uint4 d0 = *(const uint4*)(st + (2 * warp) * ROW_CB + lane * 16);
            uint4 d1 = *(const uint4*)(st + (2 * warp + 1) * ROW_CB + lane * 16);
            float4 za = *(const float4*)(zs + c * 256 + lane * 8);
            float4 zb = *(const float4*)(zs + c * 256 + lane * 8 + 4);
            float2 p0 = __bfloat1622float2(*(__nv_bfloat162*)&d0.x);
            float2 p1 = __bfloat1622float2(*(__nv_bfloat162*)&d0.y);
            float2 p2 = __bfloat1622float2(*(__nv_bfloat162*)&d0.z);
            float2 p3 = __bfloat1622float2(*(__nv_bfloat162*)&d0.w);
            acc0 += p0.x * za.x + p0.y * za.y + p1.x * za.z + p1.y * za.w
                  + p2.x * zb.x + p2.y * zb.y + p3.x * zb.z + p3.y * zb.w;
            p0 = __bfloat1622float2(*(__nv_bfloat162*)&d1.x);
            p1 = __bfloat1622float2(*(__nv_bfloat162*)&d1.y);
            p2 = __bfloat1622float2(*(__nv_bfloat162*)&d1.z);
            p3 = __bfloat1622float2(*(__nv_bfloat162*)&d1.w);
            acc1 += p0.x * za.x + p0.y * za.y + p1.x * za.z + p1.y * za.w
                  + p2.x * zb.x + p2.y * zb.y + p3.x * zb.z + p3.y * zb.w;
            if (c + 2 < NCHUNK) {
                int cc = c + 2;
                char* d = (char*)stage + (cc % 3) * CHUNK_B + lrow * ROW_CB + loff;
                const char* s = srow + cc * ROW_CB + loff;
                __pipeline_memcpy_async(d, s, 16);
                __pipeline_memcpy_async(d + 16, s + 16, 16);
                __pipeline_commit();
            }
        }

        {
            int uu0 = (r0 & 63) - u0;
            int uu1 = uu0 + 1;
            float zl  = zs[(h << 6) + lane];
            float zh2 = zs[(h << 6) + lane + 32];
            acc0 += Tss[lane * 33 + uu0] * zl + Tss[(lane + 32) * 33 + uu0] * zh2;
            acc1 += Tss[lane * 33 + uu1] * zl + Tss[(lane + 32) * 33 + uu1] * zh2;
        }
        #pragma unroll
        for (int off = 16; off; off >>= 1) {
            acc0 += __shfl_xor_sync(0xffffffffu, acc0, off);
            acc1 += __shfl_xor_sync(0xffffffffu, acc1, off);
        }
        if (lane < 2) {
            int row = r0 + lane;
            float a = lane ? acc1 : acc0;
            float zr = zs[row];
            float Azv = a + g_qr[row] * zr;
            az_s[2 * warp + lane] = Azv;
            atomicAdd(&sred[0], zr * Azv);
            atomicAdd(&sred[1], zr * g_Ap[row]);
            atomicAdd(&sred[2], g_r[row] * zr);
        }
        __syncthreads();

        if (t == 0) {
            atomicAdd(&g_zAzA[k], sred[0]);
            atomicAdd(&g_zApA[k], sred[1]);
            atomicAdd(&g_rzA[k],  sred[2]);
            __threadfence();
            atomicAdd(&g_barA[2 * k], 1);
            while (*(volatile int*)&g_barA[2 * k] < MV_BLOCKS) __nanosleep(64);
        }
        __syncthreads();

        float zAz = *(volatile float*)&g_zAzA[k];
        float zAp = *(volatile float*)&g_zApA[k];
        float rz  = *(volatile float*)&g_rzA[k];
        float beta = (k > 0 && rz_prev != 0.f) ? rz / rz_prev : 0.f;
        float pAp = zAz + 2.f * beta * zAp + beta * beta * pAp_prev;
        float alpha = (pAp != 0.f) ? rz / pAp : 0.f;
        rz_prev = rz; pAp_prev = pAp;

        if (t < 32) {
            int row = row0 + t;
            float zn = zs[row];
            float pn = zn + beta * g_p[row];
            float Apn = az_s[t] + beta * g_Ap[row];
            g_p[row] = pn; g_Ap[row] = Apn;
            g_x[row] = g_x[row] + alpha * pn;
            float rn = g_r[row] - alpha * Apn;
            g_r[row] = rn;
            g_z[row] = g_Minv[row] * rn;
            __threadfence();
        }
        __syncthreads();

        if (t == 0) {
            atomicAdd(&g_barA[2 * k + 1], 1);
            while (*(volatile int*)&g_barA[2 * k + 1] < MV_BLOCKS) __nanosleep(64);
        }
        __syncthreads();
    }
}

// ---------------- 3) SVT via ONE-SIDED Jacobi, V eliminated algebraically -------------
// C := M; rotate column pairs until C = U diag(s). Incremental norms give app/aqq;
// only apq is a fresh dot (butterfly -> all lanes, rotation computed redundantly).
// V^T = diag(1/s^2) C^T M  =>  Ltmp = C diag((s-tau)/s^3) (C^T M).
__global__ void __launch_bounds__(1024) svt_kernel(
    const float* __restrict__ thP, const float* __restrict__ vp,
    const float* __restrict__ netap, float* __restrict__ out)
{
    __shared__ float Cs[64 * 66];   // column c at Cs[c*66 + r] (66: float2-aligned pad)
    __shared__ float Ms[64 * 65];   // M row-major
    __shared__ float Tt[64 * 65];   // coef_c * (C^T M)[c][u]
    __shared__ float nrm[64], coef[64];
    __shared__ float smax_s;
    int t = threadIdx.x, warp = t >> 5, lane = t & 31;

    // load M (both layouts)
    for (int i = t; i < 4096; i += 1024) {
        int r = i >> 6, u = i & 63;
        float m = g_x[i] + thP[i];
        Ms[r * 65 + u] = m;
        Cs[u * 66 + r] = m;
    }
    __syncthreads();
    // initial column norms^2
    if (t < 64) {
        float s2 = 0.f;
        #pragma unroll 8
        for (int r = 0; r < 64; r++) { float c = Cs[t * 66 + r]; s2 += c * c; }
        nrm[t] = s2;
    }
    __syncthreads();

    for (int sw = 0; sw < SWEEPS; sw++) {
        for (int rr = 0; rr < 63; rr++) {
            int p = (warp == 0) ? 0 : (1 + ((warp - 1 + rr) % 63));
            int q = 1 + ((62 - warp + rr) % 63);
            float2 cp = *(const float2*)(Cs + p * 66 + 2 * lane);
            float2 cq = *(const float2*)(Cs + q * 66 + 2 * lane);
            float apq = cp.x * cq.x + cp.y * cq.y;
            #pragma unroll
            for (int off = 16; off; off >>= 1)
                apq += __shfl_xor_sync(0xffffffffu, apq, off);
            float app = nrm[p], aqq = nrm[q];
            if (fabsf(apq) > 1e-12f * sqrtf(app * aqq) && app * aqq > 0.f) {
                float th = (aqq - app) / (2.f * apq);
                float tt = 1.f / (fabsf(th) + sqrtf(th * th + 1.f));
                if (th < 0.f) tt = -tt;
                float c_ = rsqrtf(1.f + tt * tt);
                float s_ = tt * c_;
                float2 np, nq;
                np.x = c_ * cp.x - s_ * cq.x; np.y = c_ * cp.y - s_ * cq.y;
                nq.x = s_ * cp.x + c_ * cq.x; nq.y = s_ * cp.y + c_ * cq.y;
                *(float2*)(Cs + p * 66 + 2 * lane) = np;
                *(float2*)(Cs + q * 66 + 2 * lane) = nq;
                if (lane == 0) {
                    nrm[p] = app - tt * apq;
                    nrm[q] = aqq + tt * apq;
                }
            }
            __syncthreads();
        }
    }

    // exact norms, threshold coefficients
    if (t < 64) {
        float s2 = 0.f;
        #pragma unroll 8
        for (int r = 0; r < 64; r++) { float c = Cs[t * 66 + r]; s2 += c * c; }
        nrm[t] = s2;
    }
    __syncthreads();
    if (t < 32) {
        float m = fmaxf(nrm[t], nrm[t + 32]);
        #pragma unroll
        for (int off = 16; off; off >>= 1) m = fmaxf(m, __shfl_xor_sync(0xffffffffu, m, off));
        if (t == 0) smax_s = sqrtf(m);
    }
    __syncthreads();
    float sig = 1.f / (1.f + expf(-(*vp)));
    float tau = sig * 0.4f * smax_s;
    if (t < 64) {
        float s2 = nrm[t];
        float si = sqrtf(s2);
        coef[t] = (si > tau) ? (si - tau) / (si * s2) : 0.f;
    }
    __syncthreads();

    // Tt[c][u] = coef_c * sum_r Cs[c][r] * M[r][u]
    #pragma unroll
    for (int s4 = 0; s4 < 4; s4++) {
        int e = t + 1024 * s4;
        int c = e >> 6, u = e & 63;
        float acc = 0.f;
        #pragma unroll 8
        for (int r = 0; r < 64; r++) acc += Cs[c * 66 + r] * Ms[r * 65 + u];
        Tt[c * 65 + u] = coef[c] * acc;
    }
    __syncthreads();
    // Ltmp[r][u] = sum_c Cs[c][r] * Tt[c][u] ; Ptmp = thP + neta*(x - Ltmp)
    float neta = *netap;
    #pragma unroll
    for (int s4 = 0; s4 < 4; s4++) {
        int e = t + 1024 * s4;
        int r = e >> 6, u = e & 63;
        float acc = 0.f;
        #pragma unroll 8
        for (int c = 0; c < 64; c++) acc += Cs[c * 66 + r] * Tt[c * 65 + u];
        out[e] = acc;
        out[NN + e] = thP[e] + neta * (g_x[e] - acc);
    }
}

// ---------------- launch ----------------
extern "C" void kernel_launch(void* const* d_in, const int* in_sizes, int n_in,
                              void* d_out, int out_size) {
    const float* inp  = (const float*)d_in[0];
    const float* L    = (const float*)d_in[1];
    const void*  mask = (const void*)d_in[2];
    const float* D    = (const float*)d_in[3];
    const float* thP  = (const float*)d_in[4];
    const float* v    = (const float*)d_in[5];
    const float* neta = (const float*)d_in[6];
    const float* l1   = (const float*)d_in[7];
    const float* l2   = (const float*)d_in[8];
    const float* rho  = (const float*)d_in[9];
    const float* S    = (const float*)d_in[10];

    cudaFuncSetAttribute(cg_kernel, cudaFuncAttributeMaxDynamicSharedMemorySize, SMEM_CG);

    convert_kernel<<<2048, 256>>>(D, l1);
    setup_kernel<<<1, 1024>>>(inp, L, mask, thP, D, l1, l2, rho, S);
    cg_kernel<<<MV_BLOCKS, MV_TPB, SMEM_CG>>>();
    svt_kernel<<<1, 1024>>>(thP, v, neta, (float*)d_out);
}

// round 7
// speedup vs baseline: 2.4204x; 1.0796x over previous
#include <cuda_runtime.h>
#include <cuda_bf16.h>
#include <cuda_pipeline.h>

#define NN 4096
#define ITERS 10
#define SWEEPS 6
#define MV_BLOCKS 128
#define MV_TPB 512
#define NCHUNK 16
#define ROW_CB 512                      // bytes per row per chunk (256 bf16)
#define CHUNK_B (32 * ROW_CB)           // 16 KB per chunk stage
#define SMEM_CG (25088 + 3 * CHUNK_B)   // 74240 bytes

// ---------------- persistent device scratch (static, no runtime alloc) ----------------
__device__ __nv_bfloat16 g_D16[(size_t)NN * NN];   // lamda1 * D_tilda in bf16 (33.5 MB)
__device__ float g_qr[NN];        // q + rho
__device__ float g_Minv[NN];      // Jacobi preconditioner
__device__ float g_StS[64 * 64];  // lamda2 * S^T S
__device__ float g_x[NN], g_r[NN], g_z[NN], g_p[NN], g_Ap[NN];
__device__ float g_zAzA[ITERS], g_zApA[ITERS], g_rzA[ITERS];
__device__ int   g_barA[2 * ITERS];

// ---------------- 0) convert: g_D16 = bf16(lamda1 * D)  (DRAM-bound, big grid) -------
__global__ void __launch_bounds__(256) convert_kernel(
    const float* __restrict__ D, const float* __restrict__ l1p)
{
    float l1 = *l1p;
    size_t base = ((size_t)blockIdx.x * 256 + threadIdx.x) * 8;   // float4 index
    const float4* src = (const float4*)D;
    __nv_bfloat162* dst = (__nv_bfloat162*)g_D16;
    float4 v[8];
    #pragma unroll
    for (int i = 0; i < 8; i++) v[i] = src[base + i];
    #pragma unroll
    for (int i = 0; i < 8; i++) {
        __nv_bfloat162 lo, hi;
        lo.x = __float2bfloat16_rn(v[i].x * l1); lo.y = __float2bfloat16_rn(v[i].y * l1);
        hi.x = __float2bfloat16_rn(v[i].z * l1); hi.y = __float2bfloat16_rn(v[i].w * l1);
        dst[(base + i) * 2]     = lo;
        dst[(base + i) * 2 + 1] = hi;
    }
}

// ---------------- 1) setup: StS, b, Minv, CG state, zero reductions/barriers ----------
__global__ void __launch_bounds__(1024) setup_kernel(
    const float* __restrict__ inp, const float* __restrict__ L,
    const void* __restrict__ maskv, const float* __restrict__ thP,
    const float* __restrict__ D,
    const float* __restrict__ l1p, const float* __restrict__ l2p,
    const float* __restrict__ rhop, const float* __restrict__ S)
{
    __shared__ float Ss[64 * 65];
    __shared__ float Ts[64 * 65];
    int t = threadIdx.x;
    float l1 = *l1p, l2 = *l2p, rho = *rhop;

    // detect mask storage: 4-byte words (int32 0/1 or float 0.0/1.0) vs packed bytes
    const unsigned* maskw = (const unsigned*)maskv;
    unsigned wvd = maskw[t];
    int bad = (wvd != 0u && wvd != 1u && wvd != 0x3F800000u) ? 1 : 0;
    int bytemode = __syncthreads_or(bad);

    for (int i = t; i < 4096; i += 1024) {
        int h = i >> 6, a = i & 63;
        Ss[h * 65 + a] = S[i];
    }
    __syncthreads();
    for (int e = t; e < 4096; e += 1024) {
        int a = e >> 6, b = e & 63;
        float acc = 0.f;
        #pragma unroll 8
        for (int h = 0; h < 64; h++) acc += Ss[h * 65 + a] * Ss[h * 65 + b];
        acc *= l2;
        Ts[a * 65 + b] = acc;
        g_StS[e] = acc;
    }
    __syncthreads();
    const unsigned char* maskb = (const unsigned char*)maskv;
    for (int n = t; n < NN; n += 1024) {
        float qf;
        if (bytemode) qf = (maskb[n] != 0) ? 1.f : 0.f;
        else          qf = (maskw[n] != 0u) ? 1.f : 0.f;
        float qr = qf + rho;
        g_qr[n] = qr;
        int c = n & 63;
        float dg = D[(size_t)n * (NN + 1)];
        float denom = qr + l1 * dg + Ts[c * 65 + c];
        float minv = 1.f / denom;
        g_Minv[n] = minv;
        float bb = rho * (L[n] - thP[n]) + (qf != 0.f ? inp[n] : 0.f);
        g_r[n] = bb;
        g_z[n] = minv * bb;
        g_x[n] = 0.f; g_p[n] = 0.f; g_Ap[n] = 0.f;
    }
    if (t < ITERS) { g_zAzA[t] = 0.f; g_zApA[t] = 0.f; g_rzA[t] = 0.f; }
    if (t < 2 * ITERS) g_barA[t] = 0;
}

// ---------------- 2) PERSISTENT CG: all iterations in one kernel ---------------------
__global__ void __launch_bounds__(MV_TPB) cg_kernel()
{
    extern __shared__ __align__(16) char sm[];
    float* zs   = (float*)sm;                       // [0, 16384)
    float* Tss  = (float*)(sm + 16384);             // [16384, 24832): 64*33
    float* az_s = (float*)(sm + 24832);             // 32 floats
    float* sred = (float*)(sm + 24960);             // 3 floats
    __nv_bfloat16* stage = (__nv_bfloat16*)(sm + 25088);  // 3 x 16KB

    int t = threadIdx.x, b = blockIdx.x;
    int row0 = b * 32;
    int h = row0 >> 6;
    int u0 = (b & 1) * 32;
    int warp = t >> 5, lane = t & 31;
    int r0 = row0 + 2 * warp;

    for (int i = t; i < 64 * 32; i += MV_TPB) {
        int bb = i >> 5, uu = i & 31;
        Tss[bb * 33 + uu] = g_StS[bb * 64 + u0 + uu];
    }

    int lrow = t >> 4;
    int loff = (t & 15) * 32;
    const char* srow = (const char*)(g_D16 + (size_t)(row0 + lrow) * NN);

    float rz_prev = 0.f, pAp_prev = 0.f;

    for (int k = 0; k < ITERS; k++) {
        if (t < 3) sred[t] = 0.f;
        for (int i = t; i < NN; i += MV_TPB) zs[i] = __ldcg(&g_z[i]);

        #pragma unroll
        for (int c = 0; c < 2; c++) {
            char* d = (char*)stage + (c % 3) * CHUNK_B + lrow * ROW_CB + loff;
            const char* s = srow + c * ROW_CB + loff;
            __pipeline_memcpy_async(d, s, 16);
            __pipeline_memcpy_async(d + 16, s + 16, 16);
            __pipeline_commit();
        }
        __syncthreads();

        float acc0 = 0.f, acc1 = 0.f;
        #pragma unroll
        for (int c = 0; c < NCHUNK; c++) {
            if (c < NCHUNK - 1) __pipeline_wait_prior(1);
            else                __pipeline_wait_prior(0);
            __syncthreads();
            const char* st = (const char*)stage + (c % 3) * CHUNK_B;
            uint4 d0 = *(const uint4*)(st + (2 * warp) * ROW_CB + lane * 16);
            uint4 d1 = *(const uint4*)(st + (2 * warp + 1) * ROW_CB + lane * 16);
            float4 za = *(const float4*)(zs + c * 256 + lane * 8);
            float4 zb = *(const float4*)(zs + c * 256 + lane * 8 + 4);
            float2 p0 = __bfloat1622float2(*(__nv_bfloat162*)&d0.x);
            float2 p1 = __bfloat1622float2(*(__nv_bfloat162*)&d0.y);
            float2 p2 = __bfloat1622float2(*(__nv_bfloat162*)&d0.z);
            float2 p3 = __bfloat1622float2(*(__nv_bfloat162*)&d0.w);
            acc0 += p0.x * za.x + p0.y * za.y + p1.x * za.z + p1.y * za.w
                  + p2.x * zb.x + p2.y * zb.y + p3.x * zb.z + p3.y * zb.w;
            p0 = __bfloat1622float2(*(__nv_bfloat162*)&d1.x);
            p1 = __bfloat1622float2(*(__nv_bfloat162*)&d1.y);
            p2 = __bfloat1622float2(*(__nv_bfloat162*)&d1.z);
            p3 = __bfloat1622float2(*(__nv_bfloat162*)&d1.w);
            acc1 += p0.x * za.x + p0.y * za.y + p1.x * za.z + p1.y * za.w
                  + p2.x * zb.x + p2.y * zb.y + p3.x * zb.z + p3.y * zb.w;
            if (c + 2 < NCHUNK) {
                int cc = c + 2;
                char* d = (char*)stage + (cc % 3) * CHUNK_B + lrow * ROW_CB + loff;
                const char* s = srow + cc * ROW_CB + loff;
                __pipeline_memcpy_async(d, s, 16);
                __pipeline_memcpy_async(d + 16, s + 16, 16);
                __pipeline_commit();
            }
        }

        {
            int uu0 = (r0 & 63) - u0;
            int uu1 = uu0 + 1;
            float zl  = zs[(h << 6) + lane];
            float zh2 = zs[(h << 6) + lane + 32];
            acc0 += Tss[lane * 33 + uu0] * zl + Tss[(lane + 32) * 33 + uu0] * zh2;
            acc1 += Tss[lane * 33 + uu1] * zl + Tss[(lane + 32) * 33 + uu1] * zh2;
        }
        #pragma unroll
        for (int off = 16; off; off >>= 1) {
            acc0 += __shfl_xor_sync(0xffffffffu, acc0, off);
            acc1 += __shfl_xor_sync(0xffffffffu, acc1, off);
        }
        if (lane < 2) {
            int row = r0 + lane;
            float a = lane ? acc1 : acc0;
            float zr = zs[row];
            float Azv = a + g_qr[row] * zr;
            az_s[2 * warp + lane] = Azv;
            atomicAdd(&sred[0], zr * Azv);
            atomicAdd(&sred[1], zr * g_Ap[row]);
            atomicAdd(&sred[2], g_r[row] * zr);
        }
        __syncthreads();

        if (t == 0) {
            atomicAdd(&g_zAzA[k], sred[0]);
            atomicAdd(&g_zApA[k], sred[1]);
            atomicAdd(&g_rzA[k],  sred[2]);
            __threadfence();
            atomicAdd(&g_barA[2 * k], 1);
            while (*(volatile int*)&g_barA[2 * k] < MV_BLOCKS) __nanosleep(64);
        }
        __syncthreads();

        float zAz = *(volatile float*)&g_zAzA[k];
        float zAp = *(volatile float*)&g_zApA[k];
        float rz  = *(volatile float*)&g_rzA[k];
        float beta = (k > 0 && rz_prev != 0.f) ? rz / rz_prev : 0.f;
        float pAp = zAz + 2.f * beta * zAp + beta * beta * pAp_prev;
        float alpha = (pAp != 0.f) ? rz / pAp : 0.f;
        rz_prev = rz; pAp_prev = pAp;

        if (t < 32) {
            int row = row0 + t;
            float zn = zs[row];
            float pn = zn + beta * g_p[row];
            float Apn = az_s[t] + beta * g_Ap[row];
            g_p[row] = pn; g_Ap[row] = Apn;
            g_x[row] = g_x[row] + alpha * pn;
            float rn = g_r[row] - alpha * Apn;
            g_r[row] = rn;
            g_z[row] = g_Minv[row] * rn;
            __threadfence();
        }
        __syncthreads();

        if (t == 0) {
            atomicAdd(&g_barA[2 * k + 1], 1);
            while (*(volatile int*)&g_barA[2 * k + 1] < MV_BLOCKS) __nanosleep(64);
        }
        __syncthreads();
    }
}

// ---------------- 3) SVT: one-sided Jacobi, OCTET-parallel (4 pairs/warp) -------------
// Each octet (8 lanes) owns one column pair; lane holds 8 rows as 2 float4.
// 8 warps cover all 32 pairs -> ~4x fewer instructions/round than 1 pair/warp.
// V eliminated: Ltmp = C diag((s-tau)/s^3) (C^T M).
#define CSTR 68   // column stride (float4-aligned, padded)
__global__ void __launch_bounds__(1024) svt_kernel(
    const float* __restrict__ thP, const float* __restrict__ vp,
    const float* __restrict__ netap, float* __restrict__ out)
{
    __shared__ float Cs[64 * CSTR];   // column c at Cs[c*CSTR + r]  (17.4 KB)
    __shared__ float Ms[64 * 65];     // M row-major                 (16.6 KB)
    __shared__ float Tt[64 * 65];     // coef_c * (C^T M)[c][u]      (16.6 KB)
    __shared__ float nrm[64], coef[64];
    __shared__ float smax_s;
    int t = threadIdx.x, warp = t >> 5, lane = t & 31;
    int oct = lane >> 3, ol = lane & 7;

    // load M (both layouts)
    for (int i = t; i < 4096; i += 1024) {
        int r = i >> 6, u = i & 63;
        float m = g_x[i] + thP[i];
        Ms[r * 65 + u] = m;
        Cs[u * CSTR + r] = m;
    }
    __syncthreads();
    // initial column norms^2
    if (t < 64) {
        float s2 = 0.f;
        #pragma unroll 8
        for (int r = 0; r < 64; r++) { float c = Cs[t * CSTR + r]; s2 += c * c; }
        nrm[t] = s2;
    }
    __syncthreads();

    for (int sw = 0; sw < SWEEPS; sw++) {
        for (int rr = 0; rr < 63; rr++) {
            if (warp < 8) {
                int pid = warp * 4 + oct;   // pair id 0..31 (same tournament as before)
                int p = (pid == 0) ? 0 : (1 + ((pid - 1 + rr) % 63));
                int q = 1 + ((62 - pid + rr) % 63);
                const float4* cp4 = (const float4*)(Cs + p * CSTR + ol * 8);
                const float4* cq4 = (const float4*)(Cs + q * CSTR + ol * 8);
                float4 p0 = cp4[0], p1 = cp4[1];
                float4 q0 = cq4[0], q1 = cq4[1];
                float apq = p0.x * q0.x + p0.y * q0.y + p0.z * q0.z + p0.w * q0.w
                          + p1.x * q1.x + p1.y * q1.y + p1.z * q1.z + p1.w * q1.w;
                #pragma unroll
                for (int off = 4; off; off >>= 1)
                    apq += __shfl_xor_sync(0xffffffffu, apq, off);
                float app = nrm[p], aqq = nrm[q];   // octet-uniform smem broadcast
                if (fabsf(apq) > 1e-12f * sqrtf(app * aqq) && app * aqq > 0.f) {
                    float th = (aqq - app) / (2.f * apq);
                    float tt = 1.f / (fabsf(th) + sqrtf(th * th + 1.f));
                    if (th < 0.f) tt = -tt;
                    float c_ = rsqrtf(1.f + tt * tt);
                    float s_ = tt * c_;
                    float4 n0, n1, m0, m1;
                    n0.x = c_ * p0.x - s_ * q0.x; n0.y = c_ * p0.y - s_ * q0.y;
                    n0.z = c_ * p0.z - s_ * q0.z; n0.w = c_ * p0.w - s_ * q0.w;
                    n1.x = c_ * p1.x - s_ * q1.x; n1.y = c_ * p1.y - s_ * q1.y;
                    n1.z = c_ * p1.z - s_ * q1.z; n1.w = c_ * p1.w - s_ * q1.w;
                    m0.x = s_ * p0.x + c_ * q0.x; m0.y = s_ * p0.y + c_ * q0.y;
                    m0.z = s_ * p0.z + c_ * q0.z; m0.w = s_ * p0.w + c_ * q0.w;
                    m1.x = s_ * p1.x + c_ * q1.x; m1.y = s_ * p1.y + c_ * q1.y;
                    m1.z = s_ * p1.z + c_ * q1.z; m1.w = s_ * p1.w + c_ * q1.w;
                    float4* wp4 = (float4*)(Cs + p * CSTR + ol * 8);
                    float4* wq4 = (float4*)(Cs + q * CSTR + ol * 8);
                    wp4[0] = n0; wp4[1] = n1;
                    wq4[0] = m0; wq4[1] = m1;
                    if (ol == 0) {
                        nrm[p] = app - tt * apq;
                        nrm[q] = aqq + tt * apq;
                    }
                }
            }
            __syncthreads();
        }
    }

    // exact norms, threshold coefficients
    if (t < 64) {
        float s2 = 0.f;
        #pragma unroll 8
        for (int r = 0; r < 64; r++) { float c = Cs[t * CSTR + r]; s2 += c * c; }
        nrm[t] = s2;
    }
    __syncthreads();
    if (t < 32) {
        float m = fmaxf(nrm[t], nrm[t + 32]);
        #pragma unroll
        for (int off = 16; off; off >>= 1) m = fmaxf(m, __shfl_xor_sync(0xffffffffu, m, off));
        if (t == 0) smax_s = sqrtf(m);
    }
    __syncthreads();
    float sig = 1.f / (1.f + expf(-(*vp)));
    float tau = sig * 0.4f * smax_s;
    if (t < 64) {
        float s2 = nrm[t];
        float si = sqrtf(s2);
        coef[t] = (si > tau) ? (si - tau) / (si * s2) : 0.f;
    }
    __syncthreads();

    // Tt[c][u] = coef_c * sum_r Cs[c][r] * M[r][u]
    #pragma unroll
    for (int s4 = 0; s4 < 4; s4++) {
        int e = t + 1024 * s4;
        int c = e >> 6, u = e & 63;
        float acc = 0.f;
        #pragma unroll 8
        for (int r = 0; r < 64; r++) acc += Cs[c * CSTR + r] * Ms[r * 65 + u];
        Tt[c * 65 + u] = coef[c] * acc;
    }
    __syncthreads();
    // Ltmp[r][u] = sum_c Cs[c][r] * Tt[c][u] ; Ptmp = thP + neta*(x - Ltmp)
    float neta = *netap;
    #pragma unroll
    for (int s4 = 0; s4 < 4; s4++) {
        int e = t + 1024 * s4;
        int r = e >> 6, u = e & 63;
        float acc = 0.f;
        #pragma unroll 8
        for (int c = 0; c < 64; c++) acc += Cs[c * CSTR + r] * Tt[c * 65 + u];
        out[e] = acc;
        out[NN + e] = thP[e] + neta * (g_x[e] - acc);
    }
}

// ---------------- launch ----------------
extern "C" void kernel_launch(void* const* d_in, const int* in_sizes, int n_in,
                              void* d_out, int out_size) {
    const float* inp  = (const float*)d_in[0];
    const float* L    = (const float*)d_in[1];
    const void*  mask = (const void*)d_in[2];
    const float* D    = (const float*)d_in[3];
    const float* thP  = (const float*)d_in[4];
    const float* v    = (const float*)d_in[5];
    const float* neta = (const float*)d_in[6];
    const float* l1   = (const float*)d_in[7];
    const float* l2   = (const float*)d_in[8];
    const float* rho  = (const float*)d_in[9];
    const float* S    = (const float*)d_in[10];

    cudaFuncSetAttribute(cg_kernel, cudaFuncAttributeMaxDynamicSharedMemorySize, SMEM_CG);

    convert_kernel<<<2048, 256>>>(D, l1);
    setup_kernel<<<1, 1024>>>(inp, L, mask, thP, D, l1, l2, rho, S);
    cg_kernel<<<MV_BLOCKS, MV_TPB, SMEM_CG>>>();
    svt_kernel<<<1, 1024>>>(thP, v, neta, (float*)d_out);
}

// round 8
// speedup vs baseline: 2.4917x; 1.0295x over previous
#include <cuda_runtime.h>
#include <cuda_bf16.h>
#include <cuda_pipeline.h>

#define NN 4096
#define ITERS 10
#define SWEEPS 6
#define MV_BLOCKS 128
#define MV_TPB 512
#define NCHUNK 16
#define ROW_CB 512                      // bytes per row per chunk (256 bf16)
#define CHUNK_B (32 * ROW_CB)           // 16 KB per chunk stage
#define SMEM_CG (25088 + 3 * CHUNK_B)   // 74240 bytes

// ---------------- persistent device scratch (static, no runtime alloc) ----------------
__device__ __nv_bfloat16 g_D16[(size_t)NN * NN];   // lamda1 * D_tilda in bf16 (33.5 MB)
__device__ float g_qr[NN];        // q + rho
__device__ float g_Minv[NN];      // Jacobi preconditioner
__device__ float g_StS[64 * 64];  // lamda2 * S^T S
__device__ float g_x[NN], g_r[NN], g_z[NN], g_p[NN], g_Ap[NN];
__device__ float g_zAzA[ITERS], g_zApA[ITERS], g_rzA[ITERS];
__device__ int   g_barA[2 * ITERS];

// ---------------- 0) convert: g_D16 = bf16(lamda1 * D)  (DRAM-bound, big grid) -------
__global__ void __launch_bounds__(256) convert_kernel(
    const float* __restrict__ D, const float* __restrict__ l1p)
{
    float l1 = *l1p;
    size_t base = ((size_t)blockIdx.x * 256 + threadIdx.x) * 8;   // float4 index
    const float4* src = (const float4*)D;
    __nv_bfloat162* dst = (__nv_bfloat162*)g_D16;
    float4 v[8];
    #pragma unroll
    for (int i = 0; i < 8; i++) v[i] = src[base + i];
    #pragma unroll
    for (int i = 0; i < 8; i++) {
        __nv_bfloat162 lo, hi;
        lo.x = __float2bfloat16_rn(v[i].x * l1); lo.y = __float2bfloat16_rn(v[i].y * l1);
        hi.x = __float2bfloat16_rn(v[i].z * l1); hi.y = __float2bfloat16_rn(v[i].w * l1);
        dst[(base + i) * 2]     = lo;
        dst[(base + i) * 2 + 1] = hi;
    }
}

// ---------------- 1) setup: StS, b, Minv, CG state, zero reductions/barriers ----------
__global__ void __launch_bounds__(1024) setup_kernel(
    const float* __restrict__ inp, const float* __restrict__ L,
    const void* __restrict__ maskv, const float* __restrict__ thP,
    const float* __restrict__ D,
    const float* __restrict__ l1p, const float* __restrict__ l2p,
    const float* __restrict__ rhop, const float* __restrict__ S)
{
    __shared__ float Ss[64 * 65];
    __shared__ float Ts[64 * 65];
    int t = threadIdx.x;
    float l1 = *l1p, l2 = *l2p, rho = *rhop;

    // detect mask storage: 4-byte words (int32 0/1 or float 0.0/1.0) vs packed bytes
    const unsigned* maskw = (const unsigned*)maskv;
    unsigned wvd = maskw[t];
    int bad = (wvd != 0u && wvd != 1u && wvd != 0x3F800000u) ? 1 : 0;
    int bytemode = __syncthreads_or(bad);

    for (int i = t; i < 4096; i += 1024) {
        int h = i >> 6, a = i & 63;
        Ss[h * 65 + a] = S[i];
    }
    __syncthreads();
    for (int e = t; e < 4096; e += 1024) {
        int a = e >> 6, b = e & 63;
        float acc = 0.f;
        #pragma unroll 8
        for (int h = 0; h < 64; h++) acc += Ss[h * 65 + a] * Ss[h * 65 + b];
        acc *= l2;
        Ts[a * 65 + b] = acc;
        g_StS[e] = acc;
    }
    __syncthreads();
    const unsigned char* maskb = (const unsigned char*)maskv;
    for (int n = t; n < NN; n += 1024) {
        float qf;
        if (bytemode) qf = (maskb[n] != 0) ? 1.f : 0.f;
        else          qf = (maskw[n] != 0u) ? 1.f : 0.f;
        float qr = qf + rho;
        g_qr[n] = qr;
        int c = n & 63;
        float dg = D[(size_t)n * (NN + 1)];
        float denom = qr + l1 * dg + Ts[c * 65 + c];
        float minv = 1.f / denom;
        g_Minv[n] = minv;
        float bb = rho * (L[n] - thP[n]) + (qf != 0.f ? inp[n] : 0.f);
        g_r[n] = bb;
        g_z[n] = minv * bb;
        g_x[n] = 0.f; g_p[n] = 0.f; g_Ap[n] = 0.f;
    }
    if (t < ITERS) { g_zAzA[t] = 0.f; g_zApA[t] = 0.f; g_rzA[t] = 0.f; }
    if (t < 2 * ITERS) g_barA[t] = 0;
}

// ---------------- 2) PERSISTENT CG: all iterations in one kernel ---------------------
__global__ void __launch_bounds__(MV_TPB) cg_kernel()
{
    extern __shared__ __align__(16) char sm[];
    float* zs   = (float*)sm;                       // [0, 16384)
    float* Tss  = (float*)(sm + 16384);             // [16384, 24832): 64*33
    float* az_s = (float*)(sm + 24832);             // 32 floats
    float* sred = (float*)(sm + 24960);             // 3 floats
    __nv_bfloat16* stage = (__nv_bfloat16*)(sm + 25088);  // 3 x 16KB

    int t = threadIdx.x, b = blockIdx.x;
    int row0 = b * 32;
    int h = row0 >> 6;
    int u0 = (b & 1) * 32;
    int warp = t >> 5, lane = t & 31;
    int r0 = row0 + 2 * warp;

    for (int i = t; i < 64 * 32; i += MV_TPB) {
        int bb = i >> 5, uu = i & 31;
        Tss[bb * 33 + uu] = g_StS[bb * 64 + u0 + uu];
    }

    int lrow = t >> 4;
    int loff = (t & 15) * 32;
    const char* srow = (const char*)(g_D16 + (size_t)(row0 + lrow) * NN);

    float rz_prev = 0.f, pAp_prev = 0.f;

    for (int k = 0; k < ITERS; k++) {
        if (t < 3) sred[t] = 0.f;
        for (int i = t; i < NN; i += MV_TPB) zs[i] = __ldcg(&g_z[i]);

        #pragma unroll
        for (int c = 0; c < 2; c++) {
            char* d = (char*)stage + (c % 3) * CHUNK_B + lrow * ROW_CB + loff;
            const char* s = srow + c * ROW_CB + loff;
            __pipeline_memcpy_async(d, s, 16);
            __pipeline_memcpy_async(d + 16, s + 16, 16);
            __pipeline_commit();
        }
        __syncthreads();

        float acc0 = 0.f, acc1 = 0.f;
        #pragma unroll
        for (int c = 0; c < NCHUNK; c++) {
            if (c < NCHUNK - 1) __pipeline_wait_prior(1);
            else                __pipeline_wait_prior(0);
            __syncthreads();
            const char* st = (const char*)stage + (c % 3) * CHUNK_B;
            uint4 d0 = *(const uint4*)(st + (2 * warp) * ROW_CB + lane * 16);
            uint4 d1 = *(const uint4*)(st + (2 * warp + 1) * ROW_CB + lane * 16);
            float4 za = *(const float4*)(zs + c * 256 + lane * 8);
            float4 zb = *(const float4*)(zs + c * 256 + lane * 8 + 4);
            float2 p0 = __bfloat1622float2(*(__nv_bfloat162*)&d0.x);
            float2 p1 = __bfloat1622float2(*(__nv_bfloat162*)&d0.y);
            float2 p2 = __bfloat1622float2(*(__nv_bfloat162*)&d0.z);
            float2 p3 = __bfloat1622float2(*(__nv_bfloat162*)&d0.w);
            acc0 += p0.x * za.x + p0.y * za.y + p1.x * za.z + p1.y * za.w
                  + p2.x * zb.x + p2.y * zb.y + p3.x * zb.z + p3.y * zb.w;
            p0 = __bfloat1622float2(*(__nv_bfloat162*)&d1.x);
            p1 = __bfloat1622float2(*(__nv_bfloat162*)&d1.y);
            p2 = __bfloat1622float2(*(__nv_bfloat162*)&d1.z);
            p3 = __bfloat1622float2(*(__nv_bfloat162*)&d1.w);
            acc1 += p0.x * za.x + p0.y * za.y + p1.x * za.z + p1.y * za.w
                  + p2.x * zb.x + p2.y * zb.y + p3.x * zb.z + p3.y * zb.w;
            if (c + 2 < NCHUNK) {
                int cc = c + 2;
                char* d = (char*)stage + (cc % 3) * CHUNK_B + lrow * ROW_CB + loff;
                const char* s = srow + cc * ROW_CB + loff;
                __pipeline_memcpy_async(d, s, 16);
                __pipeline_memcpy_async(d + 16, s + 16, 16);
                __pipeline_commit();
            }
        }

        {
            int uu0 = (r0 & 63) - u0;
            int uu1 = uu0 + 1;
            float zl  = zs[(h << 6) + lane];
            float zh2 = zs[(h << 6) + lane + 32];
            acc0 += Tss[lane * 33 + uu0] * zl + Tss[(lane + 32) * 33 + uu0] * zh2;
            acc1 += Tss[lane * 33 + uu1] * zl + Tss[(lane + 32) * 33 + uu1] * zh2;
        }
        #pragma unroll
        for (int off = 16; off; off >>= 1) {
            acc0 += __shfl_xor_sync(0xffffffffu, acc0, off);
            acc1 += __shfl_xor_sync(0xffffffffu, acc1, off);
        }
        if (lane < 2) {
            int row = r0 + lane;
            float a = lane ? acc1 : acc0;
            float zr = zs[row];
            float Azv = a + g_qr[row] * zr;
            az_s[2 * warp + lane] = Azv;
            atomicAdd(&sred[0], zr * Azv);
            atomicAdd(&sred[1], zr * g_Ap[row]);
            atomicAdd(&sred[2], g_r[row] * zr);
        }
        __syncthreads();

        if (t == 0) {
            atomicAdd(&g_zAzA[k], sred[0]);
            atomicAdd(&g_zApA[k], sred[1]);
            atomicAdd(&g_rzA[k],  sred[2]);
            __threadfence();
            atomicAdd(&g_barA[2 * k], 1);
            while (*(volatile int*)&g_barA[2 * k] < MV_BLOCKS) __nanosleep(64);
        }
        __syncthreads();

        float zAz = *(volatile float*)&g_zAzA[k];
        float zAp = *(volatile float*)&g_zApA[k];
        float rz  = *(volatile float*)&g_rzA[k];
        float beta = (k > 0 && rz_prev != 0.f) ? rz / rz_prev : 0.f;
        float pAp = zAz + 2.f * beta * zAp + beta * beta * pAp_prev;
        float alpha = (pAp != 0.f) ? rz / pAp : 0.f;
        rz_prev = rz; pAp_prev = pAp;

        if (t < 32) {
            int row = row0 + t;
            float zn = zs[row];
            float pn = zn + beta * g_p[row];
            float Apn = az_s[t] + beta * g_Ap[row];
            g_p[row] = pn; g_Ap[row] = Apn;
            g_x[row] = g_x[row] + alpha * pn;
            float rn = g_r[row] - alpha * Apn;
            g_r[row] = rn;
            g_z[row] = g_Minv[row] * rn;
            __threadfence();
        }
        __syncthreads();

        if (t == 0) {
            atomicAdd(&g_barA[2 * k + 1], 1);
            while (*(volatile int*)&g_barA[2 * k + 1] < MV_BLOCKS) __nanosleep(64);
        }
        __syncthreads();
    }
}

// ---------------- 3) SVT: one-sided Jacobi, octet-parallel, conflict-free, branchless -
// Lane ol of an octet holds rows [ol*4, ol*4+4) and [32+ol*4, 32+ol*4+4) of its pair's
// columns -> per-octet float4 bank-span starts 4*(col+ol) mod 32 are all distinct
// (conflict-free LDS/STS phases). Rotation is fully branchless (identity when |apq|
// below threshold). V eliminated: Ltmp = C diag((s-tau)/s^3) (C^T M).
#define CSTR 68   // column stride in floats (float4-aligned)
__global__ void __launch_bounds__(1024) svt_kernel(
    const float* __restrict__ thP, const float* __restrict__ vp,
    const float* __restrict__ netap, float* __restrict__ out)
{
    __shared__ float Cs[64 * CSTR];   // column c at Cs[c*CSTR + r]  (17.4 KB)
    __shared__ float Ms[64 * 65];     // M row-major                 (16.6 KB)
    __shared__ float Tt[64 * 65];     // coef_c * (C^T M)[c][u]      (16.6 KB)
    __shared__ float nrm[64], coef[64];
    __shared__ float smax_s;
    int t = threadIdx.x, warp = t >> 5, lane = t & 31;
    int oct = lane >> 3, ol = lane & 7;

    // load M (both layouts)
    for (int i = t; i < 4096; i += 1024) {
        int r = i >> 6, u = i & 63;
        float m = g_x[i] + thP[i];
        Ms[r * 65 + u] = m;
        Cs[u * CSTR + r] = m;
    }
    __syncthreads();
    // initial column norms^2
    if (t < 64) {
        float s2 = 0.f;
        #pragma unroll 8
        for (int r = 0; r < 64; r++) { float c = Cs[t * CSTR + r]; s2 += c * c; }
        nrm[t] = s2;
    }
    __syncthreads();

    for (int sw = 0; sw < SWEEPS; sw++) {
        for (int rr = 0; rr < 63; rr++) {
            if (warp < 8) {
                int pid = warp * 4 + oct;   // pair id 0..31 (same tournament as before)
                int p = (pid == 0) ? 0 : (1 + ((pid - 1 + rr) % 63));
                int q = 1 + ((62 - pid + rr) % 63);
                float4* cp4 = (float4*)(Cs + p * CSTR) + ol;   // rows [4ol,4ol+4)
                float4* cq4 = (float4*)(Cs + q * CSTR) + ol;
                float4 p0 = cp4[0], p1 = cp4[8];               // rows [32+4ol, ...)
                float4 q0 = cq4[0], q1 = cq4[8];
                float apq = p0.x * q0.x + p0.y * q0.y + p0.z * q0.z + p0.w * q0.w
                          + p1.x * q1.x + p1.y * q1.y + p1.z * q1.z + p1.w * q1.w;
                #pragma unroll
                for (int off = 4; off; off >>= 1)
                    apq += __shfl_xor_sync(0xffffffffu, apq, off);
                float app = nrm[p], aqq = nrm[q];   // octet-uniform smem broadcast
                // branchless rotation: identity (c=1,s=0) when below threshold
                bool ok = fabsf(apq) > 1e-12f * __fsqrt_rn(app * aqq);
                float apqs = ok ? apq : 1.f;
                float th = (aqq - app) / (2.f * apqs);
                float tt = 1.f / (fabsf(th) + __fsqrt_rn(th * th + 1.f));
                tt = (th < 0.f) ? -tt : tt;
                tt = ok ? tt : 0.f;
                float c_ = __frsqrt_rn(1.f + tt * tt);
                float s_ = tt * c_;
                float4 n0, n1, m0, m1;
                n0.x = c_ * p0.x - s_ * q0.x; n0.y = c_ * p0.y - s_ * q0.y;
                n0.z = c_ * p0.z - s_ * q0.z; n0.w = c_ * p0.w - s_ * q0.w;
                n1.x = c_ * p1.x - s_ * q1.x; n1.y = c_ * p1.y - s_ * q1.y;
                n1.z = c_ * p1.z - s_ * q1.z; n1.w = c_ * p1.w - s_ * q1.w;
                m0.x = s_ * p0.x + c_ * q0.x; m0.y = s_ * p0.y + c_ * q0.y;
                m0.z = s_ * p0.z + c_ * q0.z; m0.w = s_ * p0.w + c_ * q0.w;
                m1.x = s_ * p1.x + c_ * q1.x; m1.y = s_ * p1.y + c_ * q1.y;
                m1.z = s_ * p1.z + c_ * q1.z; m1.w = s_ * p1.w + c_ * q1.w;
                cp4[0] = n0; cp4[8] = n1;
                cq4[0] = m0; cq4[8] = m1;
                if (ol == 0) {
                    nrm[p] = app - tt * apq;
                    nrm[q] = aqq + tt * apq;
                }
            }
            __syncthreads();
        }
    }

    // exact norms, threshold coefficients
    if (t < 64) {
        float s2 = 0.f;
        #pragma unroll 8
        for (int r = 0; r < 64; r++) { float c = Cs[t * CSTR + r]; s2 += c * c; }
        nrm[t] = s2;
    }
    __syncthreads();
    if (t < 32) {
        float m = fmaxf(nrm[t], nrm[t + 32]);
        #pragma unroll
        for (int off = 16; off; off >>= 1) m = fmaxf(m, __shfl_xor_sync(0xffffffffu, m, off));
        if (t == 0) smax_s = sqrtf(m);
    }
    __syncthreads();
    float sig = 1.f / (1.f + expf(-(*vp)));
    float tau = sig * 0.4f * smax_s;
    if (t < 64) {
        float s2 = nrm[t];
        float si = sqrtf(s2);
        coef[t] = (si > tau) ? (si - tau) / (si * s2) : 0.f;
    }
    __syncthreads();

    // Tt[c][u] = coef_c * sum_r Cs[c][r] * M[r][u]
    #pragma unroll
    for (int s4 = 0; s4 < 4; s4++) {
        int e = t + 1024 * s4;
        int c = e >> 6, u = e & 63;
        float acc = 0.f;
        #pragma unroll 8
        for (int r = 0; r < 64; r++) acc += Cs[c * CSTR + r] * Ms[r * 65 + u];
        Tt[c * 65 + u] = coef[c] * acc;
    }
    __syncthreads();
    // Ltmp[r][u] = sum_c Cs[c][r] * Tt[c][u] ; Ptmp = thP + neta*(x - Ltmp)
    float neta = *netap;
    #pragma unroll
    for (int s4 = 0; s4 < 4; s4++) {
        int e = t + 1024 * s4;
        int r = e >> 6, u = e & 63;
        float acc = 0.f;
        #pragma unroll 8
        for (int c = 0; c < 64; c++) acc += Cs[c * CSTR + r] * Tt[c * 65 + u];
        out[e] = acc;
        out[NN + e] = thP[e] + neta * (g_x[e] - acc);
    }
}

// ---------------- launch ----------------
extern "C" void kernel_launch(void* const* d_in, const int* in_sizes, int n_in,
                              void* d_out, int out_size) {
    const float* inp  = (const float*)d_in[0];
    const float* L    = (const float*)d_in[1];
    const void*  mask = (const void*)d_in[2];
    const float* D    = (const float*)d_in[3];
    const float* thP  = (const float*)d_in[4];
    const float* v    = (const float*)d_in[5];
    const float* neta = (const float*)d_in[6];
    const float* l1   = (const float*)d_in[7];
    const float* l2   = (const float*)d_in[8];
    const float* rho  = (const float*)d_in[9];
    const float* S    = (const float*)d_in[10];

    cudaFuncSetAttribute(cg_kernel, cudaFuncAttributeMaxDynamicSharedMemorySize, SMEM_CG);

    convert_kernel<<<2048, 256>>>(D, l1);
    setup_kernel<<<1, 1024>>>(inp, L, mask, thP, D, l1, l2, rho, S);
    cg_kernel<<<MV_BLOCKS, MV_TPB, SMEM_CG>>>();
    svt_kernel<<<1, 1024>>>(thP, v, neta, (float*)d_out);
}

// round 9
// speedup vs baseline: 2.9418x; 1.1806x over previous
#include <cuda_runtime.h>
#include <cuda_bf16.h>
#include <cuda_pipeline.h>

#define NN 4096
#define ITERS 8
#define SWEEPS 6
#define MV_BLOCKS 128
#define MV_TPB 512
#define NCHUNK 16
#define ROW_CB 512                      // bytes per row per chunk (256 bf16)
#define CHUNK_B (32 * ROW_CB)           // 16 KB per chunk stage
#define SMEM_CG (25088 + 3 * CHUNK_B)   // 74240 bytes

// ---------------- persistent device scratch (static, no runtime alloc) ----------------
__device__ __nv_bfloat16 g_D16[(size_t)NN * NN];   // lamda1 * D_tilda in bf16 (33.5 MB)
__device__ float g_qr[NN];        // q + rho
__device__ float g_Minv[NN];      // Jacobi preconditioner
__device__ float g_StS[64 * 64];  // lamda2 * S^T S
__device__ float g_x[NN], g_r[NN], g_z[NN], g_p[NN], g_Ap[NN];
__device__ float g_zAzA[ITERS], g_zApA[ITERS], g_rzA[ITERS];
__device__ int   g_barA[2 * ITERS];

// ---------------- 0) convert: g_D16 = bf16(lamda1 * D)  (DRAM-bound, big grid) -------
__global__ void __launch_bounds__(256) convert_kernel(
    const float* __restrict__ D, const float* __restrict__ l1p)
{
    float l1 = *l1p;
    size_t base = ((size_t)blockIdx.x * 256 + threadIdx.x) * 8;   // float4 index
    const float4* src = (const float4*)D;
    __nv_bfloat162* dst = (__nv_bfloat162*)g_D16;
    float4 v[8];
    #pragma unroll
    for (int i = 0; i < 8; i++) v[i] = src[base + i];
    #pragma unroll
    for (int i = 0; i < 8; i++) {
        __nv_bfloat162 lo, hi;
        lo.x = __float2bfloat16_rn(v[i].x * l1); lo.y = __float2bfloat16_rn(v[i].y * l1);
        hi.x = __float2bfloat16_rn(v[i].z * l1); hi.y = __float2bfloat16_rn(v[i].w * l1);
        dst[(base + i) * 2]     = lo;
        dst[(base + i) * 2 + 1] = hi;
    }
}

// ---------------- 1) setup: StS, b, Minv, CG state, zero reductions/barriers ----------
__global__ void __launch_bounds__(1024) setup_kernel(
    const float* __restrict__ inp, const float* __restrict__ L,
    const void* __restrict__ maskv, const float* __restrict__ thP,
    const float* __restrict__ D,
    const float* __restrict__ l1p, const float* __restrict__ l2p,
    const float* __restrict__ rhop, const float* __restrict__ S)
{
    __shared__ float Ss[64 * 65];
    __shared__ float Ts[64 * 65];
    int t = threadIdx.x;
    float l1 = *l1p, l2 = *l2p, rho = *rhop;

    // detect mask storage: 4-byte words (int32 0/1 or float 0.0/1.0) vs packed bytes
    const unsigned* maskw = (const unsigned*)maskv;
    unsigned wvd = maskw[t];
    int bad = (wvd != 0u && wvd != 1u && wvd != 0x3F800000u) ? 1 : 0;
    int bytemode = __syncthreads_or(bad);

    for (int i = t; i < 4096; i += 1024) {
        int h = i >> 6, a = i & 63;
        Ss[h * 65 + a] = S[i];
    }
    __syncthreads();
    for (int e = t; e < 4096; e += 1024) {
        int a = e >> 6, b = e & 63;
        float acc = 0.f;
        #pragma unroll 8
        for (int h = 0; h < 64; h++) acc += Ss[h * 65 + a] * Ss[h * 65 + b];
        acc *= l2;
        Ts[a * 65 + b] = acc;
        g_StS[e] = acc;
    }
    __syncthreads();
    const unsigned char* maskb = (const unsigned char*)maskv;
    for (int n = t; n < NN; n += 1024) {
        float qf;
        if (bytemode) qf = (maskb[n] != 0) ? 1.f : 0.f;
        else          qf = (maskw[n] != 0u) ? 1.f : 0.f;
        float qr = qf + rho;
        g_qr[n] = qr;
        int c = n & 63;
        float dg = D[(size_t)n * (NN + 1)];
        float denom = qr + l1 * dg + Ts[c * 65 + c];
        float minv = 1.f / denom;
        g_Minv[n] = minv;
        float bb = rho * (L[n] - thP[n]) + (qf != 0.f ? inp[n] : 0.f);
        g_r[n] = bb;
        g_z[n] = minv * bb;
        g_x[n] = 0.f; g_p[n] = 0.f; g_Ap[n] = 0.f;
    }
    if (t < ITERS) { g_zAzA[t] = 0.f; g_zApA[t] = 0.f; g_rzA[t] = 0.f; }
    if (t < 2 * ITERS) g_barA[t] = 0;
}

// ---------------- 2) PERSISTENT CG: all iterations in one kernel ---------------------
__global__ void __launch_bounds__(MV_TPB) cg_kernel()
{
    extern __shared__ __align__(16) char sm[];
    float* zs   = (float*)sm;                       // [0, 16384)
    float* Tss  = (float*)(sm + 16384);             // [16384, 24832): 64*33
    float* az_s = (float*)(sm + 24832);             // 32 floats
    float* sred = (float*)(sm + 24960);             // 3 floats
    __nv_bfloat16* stage = (__nv_bfloat16*)(sm + 25088);  // 3 x 16KB

    int t = threadIdx.x, b = blockIdx.x;
    int row0 = b * 32;
    int h = row0 >> 6;
    int u0 = (b & 1) * 32;
    int warp = t >> 5, lane = t & 31;
    int r0 = row0 + 2 * warp;

    for (int i = t; i < 64 * 32; i += MV_TPB) {
        int bb = i >> 5, uu = i & 31;
        Tss[bb * 33 + uu] = g_StS[bb * 64 + u0 + uu];
    }

    int lrow = t >> 4;
    int loff = (t & 15) * 32;
    const char* srow = (const char*)(g_D16 + (size_t)(row0 + lrow) * NN);

    float rz_prev = 0.f, pAp_prev = 0.f;

    for (int k = 0; k < ITERS; k++) {
        if (t < 3) sred[t] = 0.f;
        for (int i = t; i < NN; i += MV_TPB) zs[i] = __ldcg(&g_z[i]);

        #pragma unroll
        for (int c = 0; c < 2; c++) {
            char* d = (char*)stage + (c % 3) * CHUNK_B + lrow * ROW_CB + loff;
            const char* s = srow + c * ROW_CB + loff;
            __pipeline_memcpy_async(d, s, 16);
            __pipeline_memcpy_async(d + 16, s + 16, 16);
            __pipeline_commit();
        }
        __syncthreads();

        float acc0 = 0.f, acc1 = 0.f;
        #pragma unroll
        for (int c = 0; c < NCHUNK; c++) {
            if (c < NCHUNK - 1) __pipeline_wait_prior(1);
            else                __pipeline_wait_prior(0);
            __syncthreads();
            const char* st = (const char*)stage + (c % 3) * CHUNK_B;
            uint4 d0 = *(const uint4*)(st + (2 * warp) * ROW_CB + lane * 16);
            uint4 d1 = *(const uint4*)(st + (2 * warp + 1) * ROW_CB + lane * 16);
            float4 za = *(const float4*)(zs + c * 256 + lane * 8);
            float4 zb = *(const float4*)(zs + c * 256 + lane * 8 + 4);
            float2 p0 = __bfloat1622float2(*(__nv_bfloat162*)&d0.x);
            float2 p1 = __bfloat1622float2(*(__nv_bfloat162*)&d0.y);
            float2 p2 = __bfloat1622float2(*(__nv_bfloat162*)&d0.z);
            float2 p3 = __bfloat1622float2(*(__nv_bfloat162*)&d0.w);
            acc0 += p0.x * za.x + p0.y * za.y + p1.x * za.z + p1.y * za.w
                  + p2.x * zb.x + p2.y * zb.y + p3.x * zb.z + p3.y * zb.w;
            p0 = __bfloat1622float2(*(__nv_bfloat162*)&d1.x);
            p1 = __bfloat1622float2(*(__nv_bfloat162*)&d1.y);
            p2 = __bfloat1622float2(*(__nv_bfloat162*)&d1.z);
            p3 = __bfloat1622float2(*(__nv_bfloat162*)&d1.w);
            acc1 += p0.x * za.x + p0.y * za.y + p1.x * za.z + p1.y * za.w
                  + p2.x * zb.x + p2.y * zb.y + p3.x * zb.z + p3.y * zb.w;
            if (c + 2 < NCHUNK) {
                int cc = c + 2;
                char* d = (char*)stage + (cc % 3) * CHUNK_B + lrow * ROW_CB + loff;
                const char* s = srow + cc * ROW_CB + loff;
                __pipeline_memcpy_async(d, s, 16);
                __pipeline_memcpy_async(d + 16, s + 16, 16);
                __pipeline_commit();
            }
        }

        {
            int uu0 = (r0 & 63) - u0;
            int uu1 = uu0 + 1;
            float zl  = zs[(h << 6) + lane];
            float zh2 = zs[(h << 6) + lane + 32];
            acc0 += Tss[lane * 33 + uu0] * zl + Tss[(lane + 32) * 33 + uu0] * zh2;
            acc1 += Tss[lane * 33 + uu1] * zl + Tss[(lane + 32) * 33 + uu1] * zh2;
        }
        #pragma unroll
        for (int off = 16; off; off >>= 1) {
            acc0 += __shfl_xor_sync(0xffffffffu, acc0, off);
            acc1 += __shfl_xor_sync(0xffffffffu, acc1, off);
        }
        if (lane < 2) {
            int row = r0 + lane;
            float a = lane ? acc1 : acc0;
            float zr = zs[row];
            float Azv = a + g_qr[row] * zr;
            az_s[2 * warp + lane] = Azv;
            atomicAdd(&sred[0], zr * Azv);
            atomicAdd(&sred[1], zr * g_Ap[row]);
            atomicAdd(&sred[2], g_r[row] * zr);
        }
        __syncthreads();

        if (t == 0) {
            atomicAdd(&g_zAzA[k], sred[0]);
            atomicAdd(&g_zApA[k], sred[1]);
            atomicAdd(&g_rzA[k],  sred[2]);
            __threadfence();
            atomicAdd(&g_barA[2 * k], 1);
            while (*(volatile int*)&g_barA[2 * k] < MV_BLOCKS) __nanosleep(64);
        }
        __syncthreads();

        float zAz = *(volatile float*)&g_zAzA[k];
        float zAp = *(volatile float*)&g_zApA[k];
        float rz  = *(volatile float*)&g_rzA[k];
        float beta = (k > 0 && rz_prev != 0.f) ? rz / rz_prev : 0.f;
        float pAp = zAz + 2.f * beta * zAp + beta * beta * pAp_prev;
        float alpha = (pAp != 0.f) ? rz / pAp : 0.f;
        rz_prev = rz; pAp_prev = pAp;

        if (t < 32) {
            int row = row0 + t;
            float zn = zs[row];
            float pn = zn + beta * g_p[row];
            float Apn = az_s[t] + beta * g_Ap[row];
            g_p[row] = pn; g_Ap[row] = Apn;
            g_x[row] = g_x[row] + alpha * pn;
            float rn = g_r[row] - alpha * Apn;
            g_r[row] = rn;
            g_z[row] = g_Minv[row] * rn;
            __threadfence();
        }
        __syncthreads();

        if (t == 0) {
            atomicAdd(&g_barA[2 * k + 1], 1);
            while (*(volatile int*)&g_barA[2 * k + 1] < MV_BLOCKS) __nanosleep(64);
        }
        __syncthreads();
    }
}

// ---------------- 3) SVT: one-sided Jacobi, octet-parallel, short-chain ---------------
// Rotation loop runs on warps 0-7 only, synced by NAMED barrier (bar.sync 1, 256):
// idle warps (8-31) skip straight to the trailing __syncthreads and never sit on the
// per-round release path. Divisions via MUFU (__fdividef); threshold compare squared.
// V eliminated: Ltmp = C diag((s-tau)/s^3) (C^T M).
#define CSTR 68   // column stride in floats (float4-aligned)
__global__ void __launch_bounds__(1024) svt_kernel(
    const float* __restrict__ thP, const float* __restrict__ vp,
    const float* __restrict__ netap, float* __restrict__ out)
{
    __shared__ float Cs[64 * CSTR];   // column c at Cs[c*CSTR + r]  (17.4 KB)
    __shared__ float Ms[64 * 65];     // M row-major                 (16.6 KB)
    __shared__ float Tt[64 * 65];     // coef_c * (C^T M)[c][u]      (16.6 KB)
    __shared__ float nrm[64], coef[64];
    __shared__ float smax_s;
    int t = threadIdx.x, warp = t >> 5, lane = t & 31;
    int oct = lane >> 3, ol = lane & 7;

    // load M (both layouts)
    for (int i = t; i < 4096; i += 1024) {
        int r = i >> 6, u = i & 63;
        float m = g_x[i] + thP[i];
        Ms[r * 65 + u] = m;
        Cs[u * CSTR + r] = m;
    }
    __syncthreads();
    // initial column norms^2
    if (t < 64) {
        float s2 = 0.f;
        #pragma unroll 8
        for (int r = 0; r < 64; r++) { float c = Cs[t * CSTR + r]; s2 += c * c; }
        nrm[t] = s2;
    }
    __syncthreads();

    // -------- rotation loop: 8 working warps, named-barrier-synced --------
    if (t < 256) {
        for (int sw = 0; sw < SWEEPS; sw++) {
            for (int rr = 0; rr < 63; rr++) {
                int pid = warp * 4 + oct;   // pair id 0..31
                int p = (pid == 0) ? 0 : (1 + ((pid - 1 + rr) % 63));
                int q = 1 + ((62 - pid + rr) % 63);
                float4* cp4 = (float4*)(Cs + p * CSTR) + ol;   // rows [4ol,4ol+4)
                float4* cq4 = (float4*)(Cs + q * CSTR) + ol;
                float4 p0 = cp4[0], p1 = cp4[8];               // rows [32+4ol, ...)
                float4 q0 = cq4[0], q1 = cq4[8];
                float apq = p0.x * q0.x + p0.y * q0.y + p0.z * q0.z + p0.w * q0.w
                          + p1.x * q1.x + p1.y * q1.y + p1.z * q1.z + p1.w * q1.w;
                #pragma unroll
                for (int off = 4; off; off >>= 1)
                    apq += __shfl_xor_sync(0xffffffffu, apq, off);
                float app = nrm[p], aqq = nrm[q];   // octet-uniform smem broadcast
                // branchless; squared-form threshold (no sqrt on critical path)
                bool ok = apq * apq > 1e-24f * (app * aqq);
                float apqs = ok ? apq : 1.f;
                float th = __fdividef(aqq - app, 2.f * apqs);
                float tt = __fdividef(1.f, fabsf(th) + __fsqrt_rn(th * th + 1.f));
                tt = (th < 0.f) ? -tt : tt;
                tt = ok ? tt : 0.f;
                float c_ = __frsqrt_rn(1.f + tt * tt);
                float s_ = tt * c_;
                float4 n0, n1, m0, m1;
                n0.x = c_ * p0.x - s_ * q0.x; n0.y = c_ * p0.y - s_ * q0.y;
                n0.z = c_ * p0.z - s_ * q0.z; n0.w = c_ * p0.w - s_ * q0.w;
                n1.x = c_ * p1.x - s_ * q1.x; n1.y = c_ * p1.y - s_ * q1.y;
                n1.z = c_ * p1.z - s_ * q1.z; n1.w = c_ * p1.w - s_ * q1.w;
                m0.x = s_ * p0.x + c_ * q0.x; m0.y = s_ * p0.y + c_ * q0.y;
                m0.z = s_ * p0.z + c_ * q0.z; m0.w = s_ * p0.w + c_ * q0.w;
                m1.x = s_ * p1.x + c_ * q1.x; m1.y = s_ * p1.y + c_ * q1.y;
                m1.z = s_ * p1.z + c_ * q1.z; m1.w = s_ * p1.w + c_ * q1.w;
                cp4[0] = n0; cp4[8] = n1;
                cq4[0] = m0; cq4[8] = m1;
                if (ol == 0) {
                    nrm[p] = app - tt * apq;
                    nrm[q] = aqq + tt * apq;
                }
                asm volatile("bar.sync 1, 256;" ::: "memory");
            }
        }
    }
    __syncthreads();   // idle warps waited here; working warps arrive after loop

    // exact norms, threshold coefficients
    if (t < 64) {
        float s2 = 0.f;
        #pragma unroll 8
        for (int r = 0; r < 64; r++) { float c = Cs[t * CSTR + r]; s2 += c * c; }
        nrm[t] = s2;
    }
    __syncthreads();
    if (t < 32) {
        float m = fmaxf(nrm[t], nrm[t + 32]);
        #pragma unroll
        for (int off = 16; off; off >>= 1) m = fmaxf(m, __shfl_xor_sync(0xffffffffu, m, off));
        if (t == 0) smax_s = sqrtf(m);
    }
    __syncthreads();
    float sig = 1.f / (1.f + expf(-(*vp)));
    float tau = sig * 0.4f * smax_s;
    if (t < 64) {
        float s2 = nrm[t];
        float si = sqrtf(s2);
        coef[t] = (si > tau) ? (si - tau) / (si * s2) : 0.f;
    }
    __syncthreads();

    // Tt[c][u] = coef_c * sum_r Cs[c][r] * M[r][u]
    #pragma unroll
    for (int s4 = 0; s4 < 4; s4++) {
        int e = t + 1024 * s4;
        int c = e >> 6, u = e & 63;
        float acc = 0.f;
        #pragma unroll 8
        for (int r = 0; r < 64; r++) acc += Cs[c * CSTR + r] * Ms[r * 65 + u];
        Tt[c * 65 + u] = coef[c] * acc;
    }
    __syncthreads();
    // Ltmp[r][u] = sum_c Cs[c][r] * Tt[c][u] ; Ptmp = thP + neta*(x - Ltmp)
    float neta = *netap;
    #pragma unroll
    for (int s4 = 0; s4 < 4; s4++) {
        int e = t + 1024 * s4;
        int r = e >> 6, u = e & 63;
        float acc = 0.f;
        #pragma unroll 8
        for (int c = 0; c < 64; c++) acc += Cs[c * CSTR + r] * Tt[c * 65 + u];
        out[e] = acc;
        out[NN + e] = thP[e] + neta * (g_x[e] - acc);
    }
}

// ---------------- launch ----------------
extern "C" void kernel_launch(void* const* d_in, const int* in_sizes, int n_in,
                              void* d_out, int out_size) {
    const float* inp  = (const float*)d_in[0];
    const float* L    = (const float*)d_in[1];
    const void*  mask = (const void*)d_in[2];
    const float* D    = (const float*)d_in[3];
    const float* thP  = (const float*)d_in[4];
    const float* v    = (const float*)d_in[5];
    const float* neta = (const float*)d_in[6];
    const float* l1   = (const float*)d_in[7];
    const float* l2   = (const float*)d_in[8];
    const float* rho  = (const float*)d_in[9];
    const float* S    = (const float*)d_in[10];

    cudaFuncSetAttribute(cg_kernel, cudaFuncAttributeMaxDynamicSharedMemorySize, SMEM_CG);

    convert_kernel<<<2048, 256>>>(D, l1);
    setup_kernel<<<1, 1024>>>(inp, L, mask, thP, D, l1, l2, rho, S);
    cg_kernel<<<MV_BLOCKS, MV_TPB, SMEM_CG>>>();
    svt_kernel<<<1, 1024>>>(thP, v, neta, (float*)d_out);
}

// round 11
// speedup vs baseline: 3.2735x; 1.1127x over previous
#include <cuda_runtime.h>
#include <cuda_bf16.h>
#include <cuda_pipeline.h>

#define NN 4096
#define ITERS 8
#define SWEEPS 6
#define MV_BLOCKS 128
#define MV_TPB 512
#define NCHUNK 16
#define ROW_CB 512                      // bytes per row per chunk (256 bf16)
#define CHUNK_B (32 * ROW_CB)           // 16 KB per chunk stage

// dynamic smem layout for cg_kernel
#define OFF_ZS    0
#define OFF_RS    16384
#define OFF_APS   32768
#define OFF_MINV  49152
#define OFF_TSS   65536          // 64*33 floats = 8448 B
#define OFF_WRED  73984          // 16*3 floats = 192 B
#define OFF_SCL   74176          // 3 floats + pad -> 74240
#define OFF_STAGE 74240          // 3 x 16 KB
#define SMEM_CG   (OFF_STAGE + 3 * CHUNK_B)   // 123392 bytes

// ---------------- persistent device scratch (static, no runtime alloc) ----------------
__device__ __nv_bfloat16 g_D16[(size_t)NN * NN];   // lamda1 * D_tilda in bf16 (33.5 MB)
__device__ float g_qr[NN];        // q + rho
__device__ float g_Minv[NN];      // Jacobi preconditioner
__device__ float g_StS[64 * 64];  // lamda2 * S^T S
__device__ float g_x[NN], g_r[NN], g_z[NN], g_Az[NN];
__device__ int   g_barA[ITERS];

// ---------------- 0) convert: g_D16 = bf16(lamda1 * D)  (DRAM-bound, big grid) -------
__global__ void __launch_bounds__(256) convert_kernel(
    const float* __restrict__ D, const float* __restrict__ l1p)
{
    float l1 = *l1p;
    size_t base = ((size_t)blockIdx.x * 256 + threadIdx.x) * 8;   // float4 index
    const float4* src = (const float4*)D;
    __nv_bfloat162* dst = (__nv_bfloat162*)g_D16;
    float4 v[8];
    #pragma unroll
    for (int i = 0; i < 8; i++) v[i] = src[base + i];
    #pragma unroll
    for (int i = 0; i < 8; i++) {
        __nv_bfloat162 lo, hi;
        lo.x = __float2bfloat16_rn(v[i].x * l1); lo.y = __float2bfloat16_rn(v[i].y * l1);
        hi.x = __float2bfloat16_rn(v[i].z * l1); hi.y = __float2bfloat16_rn(v[i].w * l1);
        dst[(base + i) * 2]     = lo;
        dst[(base + i) * 2 + 1] = hi;
    }
}

// ---------------- 1) setup: StS, b, Minv, CG state, zero barriers --------------------
__global__ void __launch_bounds__(1024) setup_kernel(
    const float* __restrict__ inp, const float* __restrict__ L,
    const void* __restrict__ maskv, const float* __restrict__ thP,
    const float* __restrict__ D,
    const float* __restrict__ l1p, const float* __restrict__ l2p,
    const float* __restrict__ rhop, const float* __restrict__ S)
{
    __shared__ float Ss[64 * 65];
    __shared__ float Ts[64 * 65];
    int t = threadIdx.x;
    float l1 = *l1p, l2 = *l2p, rho = *rhop;

    // detect mask storage: 4-byte words (int32 0/1 or float 0.0/1.0) vs packed bytes
    const unsigned* maskw = (const unsigned*)maskv;
    unsigned wvd = maskw[t];
    int bad = (wvd != 0u && wvd != 1u && wvd != 0x3F800000u) ? 1 : 0;
    int bytemode = __syncthreads_or(bad);

    for (int i = t; i < 4096; i += 1024) {
        int h = i >> 6, a = i & 63;
        Ss[h * 65 + a] = S[i];
    }
    __syncthreads();
    for (int e = t; e < 4096; e += 1024) {
        int a = e >> 6, b = e & 63;
        float acc = 0.f;
        #pragma unroll 8
        for (int h = 0; h < 64; h++) acc += Ss[h * 65 + a] * Ss[h * 65 + b];
        acc *= l2;
        Ts[a * 65 + b] = acc;
        g_StS[e] = acc;
    }
    __syncthreads();
    const unsigned char* maskb = (const unsigned char*)maskv;
    for (int n = t; n < NN; n += 1024) {
        float qf;
        if (bytemode) qf = (maskb[n] != 0) ? 1.f : 0.f;
        else          qf = (maskw[n] != 0u) ? 1.f : 0.f;
        float qr = qf + rho;
        g_qr[n] = qr;
        int c = n & 63;
        float dg = D[(size_t)n * (NN + 1)];
        float denom = qr + l1 * dg + Ts[c * 65 + c];
        float minv = 1.f / denom;
        g_Minv[n] = minv;
        float bb = rho * (L[n] - thP[n]) + (qf != 0.f ? inp[n] : 0.f);
        g_r[n] = bb;
        g_z[n] = minv * bb;
    }
    if (t < ITERS) g_barA[t] = 0;
}

// ---------------- 2) PERSISTENT CG: one grid barrier per iteration -------------------
// Each block publishes its 32 Az values, then redundantly maintains the FULL r/z/Ap
// vectors in its own smem (identical op order in every block -> bitwise-identical
// alpha/beta everywhere; no global dot reduction, no atomics).
__global__ void __launch_bounds__(MV_TPB) cg_kernel()
{
    extern __shared__ __align__(16) char sm[];
    float* zs    = (float*)(sm + OFF_ZS);
    float* rs    = (float*)(sm + OFF_RS);
    float* Aps   = (float*)(sm + OFF_APS);
    float* Minvs = (float*)(sm + OFF_MINV);
    float* Tss   = (float*)(sm + OFF_TSS);
    float* wred  = (float*)(sm + OFF_WRED);
    float* scl   = (float*)(sm + OFF_SCL);
    __nv_bfloat16* stage = (__nv_bfloat16*)(sm + OFF_STAGE);

    int t = threadIdx.x, b = blockIdx.x;
    int row0 = b * 32;
    int h = row0 >> 6;
    int u0 = (b & 1) * 32;
    int warp = t >> 5, lane = t & 31;
    int r0 = row0 + 2 * warp;

    // init local full vectors + StS tile
    for (int i = t; i < NN; i += MV_TPB) {
        zs[i]  = __ldcg(&g_z[i]);
        rs[i]  = __ldcg(&g_r[i]);
        Minvs[i] = __ldcg(&g_Minv[i]);
        Aps[i] = 0.f;
    }
    for (int i = t; i < 64 * 32; i += MV_TPB) {
        int bb = i >> 5, uu = i & 31;
        Tss[bb * 33 + uu] = g_StS[bb * 64 + u0 + uu];
    }

    int lrow = t >> 4;
    int loff = (t & 15) * 32;
    const char* srow = (const char*)(g_D16 + (size_t)(row0 + lrow) * NN);

    float rz_prev = 0.f, pAp_prev = 0.f;
    float zr_save = 0.f, p_reg = 0.f, x_reg = 0.f;   // meaningful for lane<2 threads

    for (int k = 0; k < ITERS; k++) {
        // ---- matvec on local zs ----
        #pragma unroll
        for (int c = 0; c < 2; c++) {
            char* d = (char*)stage + (c % 3) * CHUNK_B + lrow * ROW_CB + loff;
            const char* s = srow + c * ROW_CB + loff;
            __pipeline_memcpy_async(d, s, 16);
            __pipeline_memcpy_async(d + 16, s + 16, 16);
            __pipeline_commit();
        }
        __syncthreads();   // zs/Aps/etc ready (also covers init on k=0)

        float acc0 = 0.f, acc1 = 0.f;
        #pragma unroll
        for (int c = 0; c < NCHUNK; c++) {
            if (c < NCHUNK - 1) __pipeline_wait_prior(1);
            else                __pipeline_wait_prior(0);
            __syncthreads();
            const char* st = (const char*)stage + (c % 3) * CHUNK_B;
            uint4 d0 = *(const uint4*)(st + (2 * warp) * ROW_CB + lane * 16);
            uint4 d1 = *(const uint4*)(st + (2 * warp + 1) * ROW_CB + lane * 16);
            float4 za = *(const float4*)(zs + c * 256 + lane * 8);
            float4 zb = *(const float4*)(zs + c * 256 + lane * 8 + 4);
            float2 p0 = __bfloat1622float2(*(__nv_bfloat162*)&d0.x);
            float2 p1 = __bfloat1622float2(*(__nv_bfloat162*)&d0.y);
            float2 p2 = __bfloat1622float2(*(__nv_bfloat162*)&d0.z);
            float2 p3 = __bfloat1622float2(*(__nv_bfloat162*)&d0.w);
            acc0 += p0.x * za.x + p0.y * za.y + p1.x * za.z + p1.y * za.w
                  + p2.x * zb.x + p2.y * zb.y + p3.x * zb.z + p3.y * zb.w;
            p0 = __bfloat1622float2(*(__nv_bfloat162*)&d1.x);
            p1 = __bfloat1622float2(*(__nv_bfloat162*)&d1.y);
            p2 = __bfloat1622float2(*(__nv_bfloat162*)&d1.z);
            p3 = __bfloat1622float2(*(__nv_bfloat162*)&d1.w);
            acc1 += p0.x * za.x + p0.y * za.y + p1.x * za.z + p1.y * za.w
                  + p2.x * zb.x + p2.y * zb.y + p3.x * zb.z + p3.y * zb.w;
            if (c + 2 < NCHUNK) {
                int cc = c + 2;
                char* d = (char*)stage + (cc % 3) * CHUNK_B + lrow * ROW_CB + loff;
                const char* s = srow + cc * ROW_CB + loff;
                __pipeline_memcpy_async(d, s, 16);
                __pipeline_memcpy_async(d + 16, s + 16, 16);
                __pipeline_commit();
            }
        }

        // lamda2 * (Z @ StS) term
        {
            int uu0 = (r0 & 63) - u0;
            int uu1 = uu0 + 1;
            float zl  = zs[(h << 6) + lane];
            float zh2 = zs[(h << 6) + lane + 32];
            acc0 += Tss[lane * 33 + uu0] * zl + Tss[(lane + 32) * 33 + uu0] * zh2;
            acc1 += Tss[lane * 33 + uu1] * zl + Tss[(lane + 32) * 33 + uu1] * zh2;
        }
        #pragma unroll
        for (int off = 16; off; off >>= 1) {
            acc0 += __shfl_xor_sync(0xffffffffu, acc0, off);
            acc1 += __shfl_xor_sync(0xffffffffu, acc1, off);
        }
        if (lane < 2) {
            int row = r0 + lane;
            float a = lane ? acc1 : acc0;
            zr_save = zs[row];
            float Azv = a + g_qr[row] * zr_save;
            g_Az[row] = Azv;          // publish own 32 Az values
            __threadfence();
        }
        __syncthreads();

        // ---- single grid barrier ----
        if (t == 0) {
            atomicAdd(&g_barA[k], 1);
            while (*(volatile int*)&g_barA[k] < MV_BLOCKS) __nanosleep(64);
        }
        __syncthreads();

        // ---- read full Az; local dots (identical in every block) ----
        float4 aza = __ldcg((const float4*)g_Az + 2 * t);
        float4 azb = __ldcg((const float4*)g_Az + 2 * t + 1);
        float az[8] = {aza.x, aza.y, aza.z, aza.w, azb.x, azb.y, azb.z, azb.w};
        float dzAz = 0.f, dzAp = 0.f, drz = 0.f;
        #pragma unroll
        for (int i = 0; i < 8; i++) {
            int n = t * 8 + i;
            float zn = zs[n];
            dzAz += zn * az[i];
            dzAp += zn * Aps[n];
            drz  += rs[n] * zn;
        }
        #pragma unroll
        for (int off = 16; off; off >>= 1) {
            dzAz += __shfl_xor_sync(0xffffffffu, dzAz, off);
            dzAp += __shfl_xor_sync(0xffffffffu, dzAp, off);
            drz  += __shfl_xor_sync(0xffffffffu, drz,  off);
        }
        if (lane == 0) {
            wred[warp * 3 + 0] = dzAz;
            wred[warp * 3 + 1] = dzAp;
            wred[warp * 3 + 2] = drz;
        }
        __syncthreads();
        if (warp == 0) {
            float a = (lane < 16) ? wred[lane * 3 + 0] : 0.f;
            float bq = (lane < 16) ? wred[lane * 3 + 1] : 0.f;
            float cc = (lane < 16) ? wred[lane * 3 + 2] : 0.f;
            #pragma unroll
            for (int off = 8; off; off >>= 1) {
                a  += __shfl_xor_sync(0xffffffffu, a,  off);
                bq += __shfl_xor_sync(0xffffffffu, bq, off);
                cc += __shfl_xor_sync(0xffffffffu, cc, off);
            }
            if (lane == 0) { scl[0] = a; scl[1] = bq; scl[2] = cc; }
        }
        __syncthreads();
        float zAz = scl[0], zAp = scl[1], rz = scl[2];
        float beta = (k > 0 && rz_prev != 0.f) ? rz / rz_prev : 0.f;
        float pAp = zAz + 2.f * beta * zAp + beta * beta * pAp_prev;
        float alpha = (pAp != 0.f) ? rz / pAp : 0.f;
        rz_prev = rz; pAp_prev = pAp;

        // own-row p/x (zr_save is z_k for this row, captured pre-update)
        if (lane < 2) {
            p_reg = zr_save + beta * p_reg;
            x_reg = x_reg + alpha * p_reg;
        }

        // ---- redundant full-vector update (8 rows/thread) ----
        #pragma unroll
        for (int i = 0; i < 8; i++) {
            int n = t * 8 + i;
            float Apn = az[i] + beta * Aps[n];
            Aps[n] = Apn;
            float rn = rs[n] - alpha * Apn;
            rs[n] = rn;
            zs[n] = Minvs[n] * rn;
        }
        __syncthreads();
    }

    if (lane < 2) g_x[r0 + lane] = x_reg;
}

// ---------------- 3) SVT: one-sided Jacobi, octet-parallel, one-division rotation -----
// Rotation loop on warps 0-7 with named barrier; conflict-free octet layout; branchless
// one-division tangent: t = sign(zeta)*apq/(|zeta|+sqrt(zeta^2+apq^2)), zeta=(aqq-app)/2.
// V eliminated: Ltmp = C diag((s-tau)/s^3) (C^T M).
#define CSTR 68   // column stride in floats (float4-aligned)
__global__ void __launch_bounds__(1024) svt_kernel(
    const float* __restrict__ thP, const float* __restrict__ vp,
    const float* __restrict__ netap, float* __restrict__ out)
{
    __shared__ float Cs[64 * CSTR];
    __shared__ float Ms[64 * 65];
    __shared__ float Tt[64 * 65];
    __shared__ float nrm[64], coef[64];
    __shared__ float smax_s;
    int t = threadIdx.x, warp = t >> 5, lane = t & 31;
    int oct = lane >> 3, ol = lane & 7;

    for (int i = t; i < 4096; i += 1024) {
        int r = i >> 6, u = i & 63;
        float m = g_x[i] + thP[i];
        Ms[r * 65 + u] = m;
        Cs[u * CSTR + r] = m;
    }
    __syncthreads();
    if (t < 64) {
        float s2 = 0.f;
        #pragma unroll 8
        for (int r = 0; r < 64; r++) { float c = Cs[t * CSTR + r]; s2 += c * c; }
        nrm[t] = s2;
    }
    __syncthreads();

    if (t < 256) {
        for (int sw = 0; sw < SWEEPS; sw++) {
            for (int rr = 0; rr < 63; rr++) {
                int pid = warp * 4 + oct;
                int p = (pid == 0) ? 0 : (1 + ((pid - 1 + rr) % 63));
                int q = 1 + ((62 - pid + rr) % 63);
                float4* cp4 = (float4*)(Cs + p * CSTR) + ol;
                float4* cq4 = (float4*)(Cs + q * CSTR) + ol;
                float4 p0 = cp4[0], p1 = cp4[8];
                float4 q0 = cq4[0], q1 = cq4[8];
                float apq = p0.x * q0.x + p0.y * q0.y + p0.z * q0.z + p0.w * q0.w
                          + p1.x * q1.x + p1.y * q1.y + p1.z * q1.z + p1.w * q1.w;
                #pragma unroll
                for (int off = 4; off; off >>= 1)
                    apq += __shfl_xor_sync(0xffffffffu, apq, off);
                float app = nrm[p], aqq = nrm[q];
                bool ok = apq * apq > 1e-24f * (app * aqq);
                float zeta = 0.5f * (aqq - app);
                float rad = __fsqrt_rn(zeta * zeta + apq * apq);
                float tt = __fdividef(apq, fabsf(zeta) + rad);
                tt = (zeta < 0.f) ? -tt : tt;
                tt = ok ? tt : 0.f;
                float c_ = __frsqrt_rn(1.f + tt * tt);
                float s_ = tt * c_;
                float4 n0, n1, m0, m1;
                n0.x = c_ * p0.x - s_ * q0.x; n0.y = c_ * p0.y - s_ * q0.y;
                n0.z = c_ * p0.z - s_ * q0.z; n0.w = c_ * p0.w - s_ * q0.w;
                n1.x = c_ * p1.x - s_ * q1.x; n1.y = c_ * p1.y - s_ * q1.y;
                n1.z = c_ * p1.z - s_ * q1.z; n1.w = c_ * p1.w - s_ * q1.w;
                m0.x = s_ * p0.x + c_ * q0.x; m0.y = s_ * p0.y + c_ * q0.y;
                m0.z = s_ * p0.z + c_ * q0.z; m0.w = s_ * p0.w + c_ * q0.w;
                m1.x = s_ * p1.x + c_ * q1.x; m1.y = s_ * p1.y + c_ * q1.y;
                m1.z = s_ * p1.z + c_ * q1.z; m1.w = s_ * p1.w + c_ * q1.w;
                cp4[0] = n0; cp4[8] = n1;
                cq4[0] = m0; cq4[8] = m1;
                if (ol == 0) {
                    nrm[p] = app - tt * apq;
                    nrm[q] = aqq + tt * apq;
                }
                asm volatile("bar.sync 1, 256;" ::: "memory");
            }
        }
    }
    __syncthreads();

    if (t < 64) {
        float s2 = 0.f;
        #pragma unroll 8
        for (int r = 0; r < 64; r++) { float c = Cs[t * CSTR + r]; s2 += c * c; }
        nrm[t] = s2;
    }
    __syncthreads();
    if (t < 32) {
        float m = fmaxf(nrm[t], nrm[t + 32]);
        #pragma unroll
        for (int off = 16; off; off >>= 1) m = fmaxf(m, __shfl_xor_sync(0xffffffffu, m, off));
        if (t == 0) smax_s = sqrtf(m);
    }
    __syncthreads();
    float sig = 1.f / (1.f + expf(-(*vp)));
    float tau = sig * 0.4f * smax_s;
    if (t < 64) {
        float s2 = nrm[t];
        float si = sqrtf(s2);
        coef[t] = (si > tau) ? (si - tau) / (si * s2) : 0.f;
    }
    __syncthreads();

    #pragma unroll
    for (int s4 = 0; s4 < 4; s4++) {
        int e = t + 1024 * s4;
        int c = e >> 6, u = e & 63;
        float acc = 0.f;
        #pragma unroll 8
        for (int r = 0; r < 64; r++) acc += Cs[c * CSTR + r] * Ms[r * 65 + u];
        Tt[c * 65 + u] = coef[c] * acc;
    }
    __syncthreads();
    float neta = *netap;
    #pragma unroll
    for (int s4 = 0; s4 < 4; s4++) {
        int e = t + 1024 * s4;
        int r = e >> 6, u = e & 63;
        float acc = 0.f;
        #pragma unroll 8
        for (int c = 0; c < 64; c++) acc += Cs[c * CSTR + r] * Tt[c * 65 + u];
        out[e] = acc;
        out[NN + e] = thP[e] + neta * (g_x[e] - acc);
    }
}

// ---------------- launch ----------------
extern "C" void kernel_launch(void* const* d_in, const int* in_sizes, int n_in,
                              void* d_out, int out_size) {
    const float* inp  = (const float*)d_in[0];
    const float* L    = (const float*)d_in[1];
    const void*  mask = (const void*)d_in[2];
    const float* D    = (const float*)d_in[3];
    const float* thP  = (const float*)d_in[4];
    const float* v    = (const float*)d_in[5];
    const float* neta = (const float*)d_in[6];
    const float* l1   = (const float*)d_in[7];
    const float* l2   = (const float*)d_in[8];
    const float* rho  = (const float*)d_in[9];
    const float* S    = (const float*)d_in[10];

    cudaFuncSetAttribute(cg_kernel, cudaFuncAttributeMaxDynamicSharedMemorySize, SMEM_CG);

    convert_kernel<<<2048, 256>>>(D, l1);
    setup_kernel<<<1, 1024>>>(inp, L, mask, thP, D, l1, l2, rho, S);
    cg_kernel<<<MV_BLOCKS, MV_TPB, SMEM_CG>>>();
    svt_kernel<<<1, 1024>>>(thP, v, neta, (float*)d_out);
}